// round 1
// baseline (speedup 1.0000x reference)
#include <cuda_runtime.h>
#include <math.h>

#define EMBED   1024
#define NHEAD   16
#define HD      64
#define BATCH   2
#define SEQ     2048
#define TOKENS  (BATCH * SEQ)      // 4096
#define QKV_N   (3 * EMBED)        // 3072

// Scratch (no cudaMalloc allowed)
__device__ float g_qkv[(size_t)TOKENS * QKV_N];   // 50 MB: [token][3*EMBED]
__device__ float g_attn[(size_t)TOKENS * EMBED];  // 16 MB: [token][EMBED] (B,N,H,Hd flattened)

// ---------------------------------------------------------------------------
// SGEMM (NT): C[m][n] = sum_k A[m][k] * W[n][k] + bias[n]
// A: [M,K] row-major, W: [N,K] row-major (torch Linear weight), C: [M,N]
// BM=BN=128, BK=8, TM=TN=8, 256 threads.
// ---------------------------------------------------------------------------
template <int BM, int BN, int BK, int TM, int TN>
__global__ void sgemm_nt_bias(const float* __restrict__ A,
                              const float* __restrict__ W,
                              const float* __restrict__ bias,
                              float* __restrict__ C,
                              int M, int N, int K)
{
    __shared__ float As[BK][BM];
    __shared__ float Bs[BK][BN];

    const int tid = threadIdx.x;          // 0..255
    const int tx  = tid % (BN / TN);      // 0..15
    const int ty  = tid / (BN / TN);      // 0..15
    const int m0  = blockIdx.y * BM;
    const int n0  = blockIdx.x * BN;

    // loader mapping: each thread loads one float4 of A and one of W per k-step
    const int lrow = tid >> 1;            // 0..127
    const int lk   = (tid & 1) * 4;       // 0 or 4

    float acc[TM][TN];
#pragma unroll
    for (int i = 0; i < TM; i++)
#pragma unroll
        for (int j = 0; j < TN; j++) acc[i][j] = 0.0f;

    for (int k0 = 0; k0 < K; k0 += BK) {
        float4 av = *(const float4*)(A + (size_t)(m0 + lrow) * K + k0 + lk);
        float4 wv = *(const float4*)(W + (size_t)(n0 + lrow) * K + k0 + lk);
        __syncthreads();   // previous compute done before smem overwrite
        As[lk + 0][lrow] = av.x; As[lk + 1][lrow] = av.y;
        As[lk + 2][lrow] = av.z; As[lk + 3][lrow] = av.w;
        Bs[lk + 0][lrow] = wv.x; Bs[lk + 1][lrow] = wv.y;
        Bs[lk + 2][lrow] = wv.z; Bs[lk + 3][lrow] = wv.w;
        __syncthreads();

#pragma unroll
        for (int k = 0; k < BK; k++) {
            float a[TM], b[TN];
            *(float4*)&a[0] = *(const float4*)&As[k][ty * TM];
            *(float4*)&a[4] = *(const float4*)&As[k][ty * TM + 4];
            *(float4*)&b[0] = *(const float4*)&Bs[k][tx * TN];
            *(float4*)&b[4] = *(const float4*)&Bs[k][tx * TN + 4];
#pragma unroll
            for (int i = 0; i < TM; i++)
#pragma unroll
                for (int j = 0; j < TN; j++)
                    acc[i][j] += a[i] * b[j];
        }
    }

#pragma unroll
    for (int i = 0; i < TM; i++) {
        const int m = m0 + ty * TM + i;
#pragma unroll
        for (int j = 0; j < TN; j += 4) {
            const int n = n0 + tx * TN + j;
            float4 o;
            o.x = acc[i][j + 0] + bias[n + 0];
            o.y = acc[i][j + 1] + bias[n + 1];
            o.z = acc[i][j + 2] + bias[n + 2];
            o.w = acc[i][j + 3] + bias[n + 3];
            *(float4*)(C + (size_t)m * N + n) = o;
        }
    }
}

// ---------------------------------------------------------------------------
// Flash attention (fp32, online softmax).
// One CTA handles 64 queries for one (b, h). 256 threads as 16x16 grid,
// each thread owns a 4x4 tile of S/P and of O (cols = 4 of 64 head dims).
// ---------------------------------------------------------------------------
#define PAD (HD + 1)   // 65

__global__ void flash_attn(const float* __restrict__ qkv, float* __restrict__ out)
{
    extern __shared__ float sm[];
    float (*Qs)[PAD] = (float(*)[PAD])(sm);
    float (*Ks)[PAD] = (float(*)[PAD])(sm + 64 * PAD);
    float (*Vs)[PAD] = (float(*)[PAD])(sm + 2 * 64 * PAD);
    float (*Ps)[PAD] = (float(*)[PAD])(sm + 3 * 64 * PAD);

    const int tid = threadIdx.x;
    const int tx  = tid & 15;
    const int ty  = tid >> 4;
    const int r0  = ty * 4;   // local query rows
    const int c0  = tx * 4;   // local key cols / head-dim cols

    const int qtile = blockIdx.x;      // 0..31
    const int h     = blockIdx.y;      // 0..15
    const int b     = blockIdx.z;      // 0..1
    const int q0    = qtile * 64;

    const size_t base = (size_t)b * SEQ * QKV_N;
    const int qcol = h * HD;
    const int kcol = EMBED + h * HD;
    const int vcol = 2 * EMBED + h * HD;

    // Load Q tile, pre-scaled by 1/sqrt(Hd)
    {
        const int r = tid >> 4;          // 0..15
        const int d = (tid & 15) * 4;
#pragma unroll
        for (int rr = r; rr < 64; rr += 16) {
            float4 v = *(const float4*)(qkv + base + (size_t)(q0 + rr) * QKV_N + qcol + d);
            Qs[rr][d + 0] = v.x * 0.125f;
            Qs[rr][d + 1] = v.y * 0.125f;
            Qs[rr][d + 2] = v.z * 0.125f;
            Qs[rr][d + 3] = v.w * 0.125f;
        }
    }

    float m_i[4], l_i[4], o[4][4];
#pragma unroll
    for (int i = 0; i < 4; i++) {
        m_i[i] = -INFINITY; l_i[i] = 0.0f;
#pragma unroll
        for (int j = 0; j < 4; j++) o[i][j] = 0.0f;
    }

    for (int j0 = 0; j0 < SEQ; j0 += 64) {
        __syncthreads();   // previous iter done reading Ks/Vs/Ps (first iter: Q-load visible too)
        // Load K, V tiles
        {
            const int r = tid >> 4;
            const int d = (tid & 15) * 4;
#pragma unroll
            for (int rr = r; rr < 64; rr += 16) {
                float4 kv = *(const float4*)(qkv + base + (size_t)(j0 + rr) * QKV_N + kcol + d);
                float4 vv = *(const float4*)(qkv + base + (size_t)(j0 + rr) * QKV_N + vcol + d);
                Ks[rr][d + 0] = kv.x; Ks[rr][d + 1] = kv.y;
                Ks[rr][d + 2] = kv.z; Ks[rr][d + 3] = kv.w;
                Vs[rr][d + 0] = vv.x; Vs[rr][d + 1] = vv.y;
                Vs[rr][d + 2] = vv.z; Vs[rr][d + 3] = vv.w;
            }
        }
        __syncthreads();

        // S = (Q * scale) @ K^T  (4x4 per thread)
        float s[4][4];
#pragma unroll
        for (int i = 0; i < 4; i++)
#pragma unroll
            for (int j = 0; j < 4; j++) s[i][j] = 0.0f;

#pragma unroll 8
        for (int d = 0; d < HD; d++) {
            float qv[4], kv[4];
#pragma unroll
            for (int i = 0; i < 4; i++) qv[i] = Qs[r0 + i][d];
#pragma unroll
            for (int j = 0; j < 4; j++) kv[j] = Ks[c0 + j][d];
#pragma unroll
            for (int i = 0; i < 4; i++)
#pragma unroll
                for (int j = 0; j < 4; j++)
                    s[i][j] += qv[i] * kv[j];
        }

        // Online softmax update per local row (reduce across 16 lanes = half warp)
        float alpha[4];
#pragma unroll
        for (int i = 0; i < 4; i++) {
            float mx = fmaxf(fmaxf(s[i][0], s[i][1]), fmaxf(s[i][2], s[i][3]));
#pragma unroll
            for (int off = 8; off >= 1; off >>= 1)
                mx = fmaxf(mx, __shfl_xor_sync(0xffffffffu, mx, off));
            float m_new = fmaxf(m_i[i], mx);
            alpha[i] = __expf(m_i[i] - m_new);   // exp(-inf)=0 on first tile
            float rs = 0.0f;
#pragma unroll
            for (int j = 0; j < 4; j++) {
                s[i][j] = __expf(s[i][j] - m_new);
                rs += s[i][j];
            }
#pragma unroll
            for (int off = 8; off >= 1; off >>= 1)
                rs += __shfl_xor_sync(0xffffffffu, rs, off);
            l_i[i] = l_i[i] * alpha[i] + rs;
            m_i[i] = m_new;
            // rescale O row, store P to smem
#pragma unroll
            for (int j = 0; j < 4; j++) {
                o[i][j] *= alpha[i];
                Ps[r0 + i][c0 + j] = s[i][j];
            }
        }
        __syncthreads();   // Ps visible to all (and all done reading Ks)

        // O += P @ V  (4 rows x 4 dim-cols per thread)
#pragma unroll 8
        for (int kk = 0; kk < 64; kk++) {
            float pv[4], vv[4];
#pragma unroll
            for (int i = 0; i < 4; i++) pv[i] = Ps[r0 + i][kk];
#pragma unroll
            for (int j = 0; j < 4; j++) vv[j] = Vs[kk][c0 + j];
#pragma unroll
            for (int i = 0; i < 4; i++)
#pragma unroll
                for (int j = 0; j < 4; j++)
                    o[i][j] += pv[i] * vv[j];
        }
    }

    // Normalize and write out: out[(b*SEQ + q)][h*HD + d]
#pragma unroll
    for (int i = 0; i < 4; i++) {
        const float inv = 1.0f / l_i[i];
        const size_t row = (size_t)(b * SEQ + q0 + r0 + i) * EMBED + h * HD + c0;
        float4 ov;
        ov.x = o[i][0] * inv; ov.y = o[i][1] * inv;
        ov.z = o[i][2] * inv; ov.w = o[i][3] * inv;
        *(float4*)(out + row) = ov;
    }
}

// ---------------------------------------------------------------------------
extern "C" void kernel_launch(void* const* d_in, const int* in_sizes, int n_in,
                              void* d_out, int out_size)
{
    const float* x     = (const float*)d_in[0];
    const float* W_qkv = (const float*)d_in[1];
    const float* b_qkv = (const float*)d_in[2];
    const float* W_p   = (const float*)d_in[3];
    const float* b_p   = (const float*)d_in[4];
    float* out = (float*)d_out;

    float *qkv, *attn;
    cudaGetSymbolAddress((void**)&qkv,  g_qkv);
    cudaGetSymbolAddress((void**)&attn, g_attn);

    // 1) QKV projection: [4096, 3072]
    sgemm_nt_bias<128, 128, 8, 8, 8>
        <<<dim3(QKV_N / 128, TOKENS / 128), 256>>>(x, W_qkv, b_qkv, qkv,
                                                   TOKENS, QKV_N, EMBED);

    // 2) Flash attention -> [4096, 1024]
    const int smem = 4 * 64 * PAD * (int)sizeof(float);  // ~65 KB
    cudaFuncSetAttribute(flash_attn, cudaFuncAttributeMaxDynamicSharedMemorySize, smem);
    flash_attn<<<dim3(SEQ / 64, NHEAD, BATCH), 256, smem>>>(qkv, attn);

    // 3) Output projection: [4096, 1024]
    sgemm_nt_bias<128, 128, 8, 8, 8>
        <<<dim3(EMBED / 128, TOKENS / 128), 256>>>(attn, W_p, b_p, out,
                                                   TOKENS, EMBED, EMBED);
}

// round 3
// speedup vs baseline: 1.0143x; 1.0143x over previous
#include <cuda_runtime.h>
#include <cuda_bf16.h>
#include <math.h>
#include <stdint.h>

#define EMBED   1024
#define NHEAD   16
#define HD      64
#define BATCH   2
#define SEQ     2048
#define TOKENS  (BATCH * SEQ)      // 4096
#define QKV_N   (3 * EMBED)        // 3072

// ---------------------------------------------------------------------------
// Scratch (__device__ globals; no cudaMalloc allowed)
// ---------------------------------------------------------------------------
__device__ float g_qkv [(size_t)TOKENS * QKV_N];
__device__ float g_attn[(size_t)TOKENS * EMBED];
__device__ __nv_bfloat16 g_x_hi   [(size_t)TOKENS * EMBED];
__device__ __nv_bfloat16 g_x_lo   [(size_t)TOKENS * EMBED];
__device__ __nv_bfloat16 g_wqkv_hi[(size_t)QKV_N * EMBED];
__device__ __nv_bfloat16 g_wqkv_lo[(size_t)QKV_N * EMBED];
__device__ __nv_bfloat16 g_wp_hi  [(size_t)EMBED * EMBED];
__device__ __nv_bfloat16 g_wp_lo  [(size_t)EMBED * EMBED];
__device__ __nv_bfloat16 g_at_hi  [(size_t)TOKENS * EMBED];
__device__ __nv_bfloat16 g_at_lo  [(size_t)TOKENS * EMBED];

// ---------------------------------------------------------------------------
// helpers
// ---------------------------------------------------------------------------
__device__ __forceinline__ uint32_t smem_u32(const void* p) {
    uint32_t a;
    asm("{ .reg .u64 t; cvta.to.shared.u64 t, %1; cvt.u32.u64 %0, t; }"
        : "=r"(a) : "l"(p));
    return a;
}
__device__ __forceinline__ void cp_async16(uint32_t s, const void* g) {
    asm volatile("cp.async.cg.shared.global [%0], [%1], 16;" :: "r"(s), "l"(g));
}
#define CP_COMMIT() asm volatile("cp.async.commit_group;" ::: "memory")
#define CP_WAIT1()  asm volatile("cp.async.wait_group 1;" ::: "memory")
#define CP_WAIT0()  asm volatile("cp.async.wait_group 0;" ::: "memory")

__device__ __forceinline__ void ldm_x4(uint32_t* r, uint32_t addr) {
    asm volatile("ldmatrix.sync.aligned.m8n8.x4.shared.b16 {%0,%1,%2,%3}, [%4];"
                 : "=r"(r[0]), "=r"(r[1]), "=r"(r[2]), "=r"(r[3]) : "r"(addr));
}
__device__ __forceinline__ void mma_bf16(float* c, const uint32_t* a,
                                         uint32_t b0, uint32_t b1) {
    asm volatile("mma.sync.aligned.m16n8k16.row.col.f32.bf16.bf16.f32 "
                 "{%0,%1,%2,%3}, {%4,%5,%6,%7}, {%8,%9}, {%0,%1,%2,%3};"
                 : "+f"(c[0]), "+f"(c[1]), "+f"(c[2]), "+f"(c[3])
                 : "r"(a[0]), "r"(a[1]), "r"(a[2]), "r"(a[3]), "r"(b0), "r"(b1));
}

// f32x2 packed math (accepted by compute_103 ptxas; verified in R2 error log)
typedef unsigned long long u64;
__device__ __forceinline__ u64 pack2(float a, float b) {
    u64 r; asm("mov.b64 %0, {%1,%2};" : "=l"(r) : "f"(a), "f"(b)); return r;
}
__device__ __forceinline__ void unpack2(u64 v, float& a, float& b) {
    asm("mov.b64 {%0,%1}, %2;" : "=f"(a), "=f"(b) : "l"(v));
}
__device__ __forceinline__ void fma2(u64& d, u64 a, u64 b) {
    asm("fma.rn.f32x2 %0, %1, %2, %0;" : "+l"(d) : "l"(a), "l"(b));
}
__device__ __forceinline__ void mul2(u64& d, u64 a) {
    asm("mul.rn.f32x2 %0, %0, %1;" : "+l"(d) : "l"(a));
}

// ---------------------------------------------------------------------------
// fp32 -> bf16 hi/lo split
// ---------------------------------------------------------------------------
__global__ void split_kernel(const float4* __restrict__ in,
                             __nv_bfloat162* __restrict__ hi,
                             __nv_bfloat162* __restrict__ lo, int n4)
{
    int i = blockIdx.x * blockDim.x + threadIdx.x;
    if (i >= n4) return;
    float4 v = in[i];
    __nv_bfloat16 h0 = __float2bfloat16(v.x), h1 = __float2bfloat16(v.y);
    __nv_bfloat16 h2 = __float2bfloat16(v.z), h3 = __float2bfloat16(v.w);
    __nv_bfloat16 l0 = __float2bfloat16(v.x - __bfloat162float(h0));
    __nv_bfloat16 l1 = __float2bfloat16(v.y - __bfloat162float(h1));
    __nv_bfloat16 l2 = __float2bfloat16(v.z - __bfloat162float(h2));
    __nv_bfloat16 l3 = __float2bfloat16(v.w - __bfloat162float(h3));
    hi[2 * i + 0] = __halves2bfloat162(h0, h1);
    hi[2 * i + 1] = __halves2bfloat162(h2, h3);
    lo[2 * i + 0] = __halves2bfloat162(l0, l1);
    lo[2 * i + 1] = __halves2bfloat162(l2, l3);
}

// ---------------------------------------------------------------------------
// HMMA bf16x3 GEMM: C[m][n] = sum_k A[m][k]*W[n][k] + bias[n]
// C = Ah*Wh + Ah*Wl + Al*Wh (fp32 accum). CTA 128x128, BK=32, 8 warps (64x32),
// cp.async double buffer, padded smem rows (64B data + 16B pad, conflict-free).
// ---------------------------------------------------------------------------
#define ROWB   80          // bytes per smem row (32 bf16 + 8 pad)
#define TILE_B (128 * ROWB)    // 10240
#define STG_B  (4 * TILE_B)    // Ah, Al, Bh, Bl
#define G_SMEM (2 * STG_B)     // 81920

__global__ __launch_bounds__(256, 1)
void gemm_hmma_x3(const __nv_bfloat16* __restrict__ Ah, const __nv_bfloat16* __restrict__ Al,
                  const __nv_bfloat16* __restrict__ Bh, const __nv_bfloat16* __restrict__ Bl,
                  const float* __restrict__ bias, float* __restrict__ C,
                  int M, int N, int K)
{
    extern __shared__ char smem[];
    const uint32_t sb = smem_u32(smem);
    const int tid  = threadIdx.x;
    const int wid  = tid >> 5;
    const int lane = tid & 31;
    const int warp_m = wid & 1;        // 0..1 -> 64 rows each
    const int warp_n = wid >> 1;       // 0..3 -> 32 cols each
    const int m0 = blockIdx.y * 128;
    const int n0 = blockIdx.x * 128;

    // loader mapping: thread t covers rows t/4 and t/4+64, 16B col chunk t%4
    const int lr = tid >> 2;
    const int lc = (tid & 3) * 16;     // byte offset within 64B row

    const __nv_bfloat16* gA[4] = { Ah + (size_t)m0 * K, Al + (size_t)m0 * K,
                                   Bh + (size_t)n0 * K, Bl + (size_t)n0 * K };

    float acc[4][4][4];
#pragma unroll
    for (int i = 0; i < 4; i++)
#pragma unroll
        for (int j = 0; j < 4; j++)
#pragma unroll
            for (int f = 0; f < 4; f++) acc[i][j][f] = 0.0f;

    const int nk = K >> 5;   // BK = 32

    // prefetch stage 0
#pragma unroll
    for (int t = 0; t < 4; t++) {
        uint32_t sT = sb + t * TILE_B;
        cp_async16(sT + lr * ROWB + lc,        (const char*)(gA[t] + (size_t)lr * K) + lc);
        cp_async16(sT + (lr + 64) * ROWB + lc, (const char*)(gA[t] + (size_t)(lr + 64) * K) + lc);
    }
    CP_COMMIT();

    // ldmatrix per-lane offsets
    const uint32_t a_off = (uint32_t)(warp_m * 64 + (lane & 15)) * ROWB + (lane >> 4) * 16;
    const uint32_t b_off = (uint32_t)(warp_n * 32 + (lane & 15)) * ROWB + (lane >> 4) * 16;

    for (int c = 0; c < nk; c++) {
        const int buf = c & 1;
        if (c + 1 < nk) {
            const int kb = (c + 1) * 64;   // byte offset into K (32 halves)
#pragma unroll
            for (int t = 0; t < 4; t++) {
                uint32_t sT = sb + (buf ^ 1) * STG_B + t * TILE_B;
                cp_async16(sT + lr * ROWB + lc,        (const char*)(gA[t] + (size_t)lr * K) + kb + lc);
                cp_async16(sT + (lr + 64) * ROWB + lc, (const char*)(gA[t] + (size_t)(lr + 64) * K) + kb + lc);
            }
            CP_COMMIT();
            CP_WAIT1();
        } else {
            CP_WAIT0();
        }
        __syncthreads();

        const uint32_t st = sb + buf * STG_B;
#pragma unroll
        for (int ks = 0; ks < 2; ks++) {
            const uint32_t ko = ks * 32;   // 16 halves
            uint32_t ah[4][4], al[4][4], bh[2][4], bl[2][4];
#pragma unroll
            for (int mt = 0; mt < 4; mt++) {
                ldm_x4(ah[mt], st + 0 * TILE_B + a_off + mt * 16 * ROWB + ko);
                ldm_x4(al[mt], st + 1 * TILE_B + a_off + mt * 16 * ROWB + ko);
            }
#pragma unroll
            for (int bt = 0; bt < 2; bt++) {
                ldm_x4(bh[bt], st + 2 * TILE_B + b_off + bt * 16 * ROWB + ko);
                ldm_x4(bl[bt], st + 3 * TILE_B + b_off + bt * 16 * ROWB + ko);
            }
#pragma unroll
            for (int mt = 0; mt < 4; mt++)
#pragma unroll
                for (int nt = 0; nt < 4; nt++) {
                    const int bt = nt >> 1, p = nt & 1;
                    mma_bf16(acc[mt][nt], ah[mt], bh[bt][p], bh[bt][p + 2]);
                    mma_bf16(acc[mt][nt], ah[mt], bl[bt][p], bl[bt][p + 2]);
                    mma_bf16(acc[mt][nt], al[mt], bh[bt][p], bh[bt][p + 2]);
                }
        }
        __syncthreads();
    }

    // epilogue: direct float2 stores + bias
    const int gr = lane >> 2;
    const int gc = (lane & 3) << 1;
#pragma unroll
    for (int mt = 0; mt < 4; mt++) {
        const int row = m0 + warp_m * 64 + mt * 16 + gr;
#pragma unroll
        for (int nt = 0; nt < 4; nt++) {
            const int col = n0 + warp_n * 32 + nt * 8 + gc;
            const float b0 = bias[col], b1 = bias[col + 1];
            float2 v0 = make_float2(acc[mt][nt][0] + b0, acc[mt][nt][1] + b1);
            float2 v1 = make_float2(acc[mt][nt][2] + b0, acc[mt][nt][3] + b1);
            *(float2*)(C + (size_t)row * N + col)       = v0;
            *(float2*)(C + (size_t)(row + 8) * N + col) = v1;
        }
    }
}

// ---------------------------------------------------------------------------
// Flash attention, fp32 math via packed f32x2 FMAs.
// ---------------------------------------------------------------------------
#define PAD 68

__global__ __launch_bounds__(256)
void flash_attn(const float* __restrict__ qkv, float* __restrict__ out)
{
    extern __shared__ float sm[];
    float (*Qs)[PAD] = (float(*)[PAD])(sm);
    float (*Ks)[PAD] = (float(*)[PAD])(sm + 64 * PAD);
    float (*Vs)[PAD] = (float(*)[PAD])(sm + 2 * 64 * PAD);
    float (*Ps)[PAD] = (float(*)[PAD])(sm + 3 * 64 * PAD);

    const int tid = threadIdx.x;
    const int tx  = tid & 15;
    const int ty  = tid >> 4;
    const int r0  = ty * 4;
    const int c0  = tx * 4;

    const int q0 = blockIdx.x * 64;
    const int h  = blockIdx.y;
    const int b  = blockIdx.z;

    const size_t base = (size_t)b * SEQ * QKV_N;
    const int qcol = h * HD;
    const int kcol = EMBED + h * HD;
    const int vcol = 2 * EMBED + h * HD;

    {
        const int r = tid >> 4;
        const int d = (tid & 15) * 4;
#pragma unroll
        for (int rr = r; rr < 64; rr += 16) {
            float4 v = *(const float4*)(qkv + base + (size_t)(q0 + rr) * QKV_N + qcol + d);
            v.x *= 0.125f; v.y *= 0.125f; v.z *= 0.125f; v.w *= 0.125f;
            *(float4*)&Qs[rr][d] = v;
        }
    }

    float m_i[4], l_i[4];
    u64 o2[4][4];
#pragma unroll
    for (int i = 0; i < 4; i++) {
        m_i[i] = -INFINITY; l_i[i] = 0.0f;
#pragma unroll
        for (int j = 0; j < 4; j++) o2[i][j] = 0ULL;
    }

    for (int j0 = 0; j0 < SEQ; j0 += 64) {
        __syncthreads();
        {
            const int r = tid >> 4;
            const int d = (tid & 15) * 4;
#pragma unroll
            for (int rr = r; rr < 64; rr += 16) {
                float4 kv = *(const float4*)(qkv + base + (size_t)(j0 + rr) * QKV_N + kcol + d);
                float4 vv = *(const float4*)(qkv + base + (size_t)(j0 + rr) * QKV_N + vcol + d);
                *(float4*)&Ks[rr][d] = kv;
                *(float4*)&Vs[rr][d] = vv;
            }
        }
        __syncthreads();

        u64 s2[4][4];
#pragma unroll
        for (int i = 0; i < 4; i++)
#pragma unroll
            for (int j = 0; j < 4; j++) s2[i][j] = 0ULL;

#pragma unroll
        for (int d = 0; d < HD; d += 2) {
            u64 q2[4], k2[4];
#pragma unroll
            for (int i = 0; i < 4; i++) q2[i] = *(const u64*)&Qs[r0 + i][d];
#pragma unroll
            for (int j = 0; j < 4; j++) k2[j] = *(const u64*)&Ks[c0 + j][d];
#pragma unroll
            for (int i = 0; i < 4; i++)
#pragma unroll
                for (int j = 0; j < 4; j++)
                    fma2(s2[i][j], q2[i], k2[j]);
        }

        float s[4][4];
#pragma unroll
        for (int i = 0; i < 4; i++)
#pragma unroll
            for (int j = 0; j < 4; j++) {
                float a, bb; unpack2(s2[i][j], a, bb);
                s[i][j] = a + bb;
            }

#pragma unroll
        for (int i = 0; i < 4; i++) {
            float mx = fmaxf(fmaxf(s[i][0], s[i][1]), fmaxf(s[i][2], s[i][3]));
#pragma unroll
            for (int off = 8; off >= 1; off >>= 1)
                mx = fmaxf(mx, __shfl_xor_sync(0xffffffffu, mx, off));
            float m_new = fmaxf(m_i[i], mx);
            float alpha = __expf(m_i[i] - m_new);
            float rs = 0.0f;
#pragma unroll
            for (int j = 0; j < 4; j++) {
                s[i][j] = __expf(s[i][j] - m_new);
                rs += s[i][j];
            }
#pragma unroll
            for (int off = 8; off >= 1; off >>= 1)
                rs += __shfl_xor_sync(0xffffffffu, rs, off);
            l_i[i] = l_i[i] * alpha + rs;
            m_i[i] = m_new;
            u64 a2 = pack2(alpha, alpha);
#pragma unroll
            for (int j = 0; j < 4; j++) mul2(o2[i][j], a2);
            *(float4*)&Ps[r0 + i][c0] = make_float4(s[i][0], s[i][1], s[i][2], s[i][3]);
        }
        __syncthreads();

#pragma unroll
        for (int kk = 0; kk < 64; kk += 2) {
            u64 p2[4];
#pragma unroll
            for (int i = 0; i < 4; i++) p2[i] = *(const u64*)&Ps[r0 + i][kk];
            float4 va = *(const float4*)&Vs[kk][c0];
            float4 vb = *(const float4*)&Vs[kk + 1][c0];
            u64 v2[4];
            v2[0] = pack2(va.x, vb.x); v2[1] = pack2(va.y, vb.y);
            v2[2] = pack2(va.z, vb.z); v2[3] = pack2(va.w, vb.w);
#pragma unroll
            for (int i = 0; i < 4; i++)
#pragma unroll
                for (int j = 0; j < 4; j++)
                    fma2(o2[i][j], p2[i], v2[j]);
        }
    }

#pragma unroll
    for (int i = 0; i < 4; i++) {
        const float inv = 1.0f / l_i[i];
        const size_t row = (size_t)(b * SEQ + q0 + r0 + i) * EMBED + h * HD + c0;
        float4 ov;
        float a, bb;
        unpack2(o2[i][0], a, bb); ov.x = (a + bb) * inv;
        unpack2(o2[i][1], a, bb); ov.y = (a + bb) * inv;
        unpack2(o2[i][2], a, bb); ov.z = (a + bb) * inv;
        unpack2(o2[i][3], a, bb); ov.w = (a + bb) * inv;
        *(float4*)(out + row) = ov;
    }
}

// ---------------------------------------------------------------------------
extern "C" void kernel_launch(void* const* d_in, const int* in_sizes, int n_in,
                              void* d_out, int out_size)
{
    const float* x     = (const float*)d_in[0];
    const float* W_qkv = (const float*)d_in[1];
    const float* b_qkv = (const float*)d_in[2];
    const float* W_p   = (const float*)d_in[3];
    const float* b_p   = (const float*)d_in[4];
    float* out = (float*)d_out;

    float *qkv, *attn;
    __nv_bfloat16 *x_hi, *x_lo, *wq_hi, *wq_lo, *wp_hi, *wp_lo, *at_hi, *at_lo;
    cudaGetSymbolAddress((void**)&qkv,   g_qkv);
    cudaGetSymbolAddress((void**)&attn,  g_attn);
    cudaGetSymbolAddress((void**)&x_hi,  g_x_hi);
    cudaGetSymbolAddress((void**)&x_lo,  g_x_lo);
    cudaGetSymbolAddress((void**)&wq_hi, g_wqkv_hi);
    cudaGetSymbolAddress((void**)&wq_lo, g_wqkv_lo);
    cudaGetSymbolAddress((void**)&wp_hi, g_wp_hi);
    cudaGetSymbolAddress((void**)&wp_lo, g_wp_lo);
    cudaGetSymbolAddress((void**)&at_hi, g_at_hi);
    cudaGetSymbolAddress((void**)&at_lo, g_at_lo);

    cudaFuncSetAttribute(gemm_hmma_x3, cudaFuncAttributeMaxDynamicSharedMemorySize, G_SMEM);
    cudaFuncSetAttribute(flash_attn,  cudaFuncAttributeMaxDynamicSharedMemorySize,
                         4 * 64 * PAD * (int)sizeof(float));

    // splits
    {
        int n4 = TOKENS * EMBED / 4;
        split_kernel<<<(n4 + 255) / 256, 256>>>((const float4*)x,
            (__nv_bfloat162*)x_hi, (__nv_bfloat162*)x_lo, n4);
    }
    {
        int n4 = QKV_N * EMBED / 4;
        split_kernel<<<(n4 + 255) / 256, 256>>>((const float4*)W_qkv,
            (__nv_bfloat162*)wq_hi, (__nv_bfloat162*)wq_lo, n4);
    }
    {
        int n4 = EMBED * EMBED / 4;
        split_kernel<<<(n4 + 255) / 256, 256>>>((const float4*)W_p,
            (__nv_bfloat162*)wp_hi, (__nv_bfloat162*)wp_lo, n4);
    }

    // QKV projection
    gemm_hmma_x3<<<dim3(QKV_N / 128, TOKENS / 128), 256, G_SMEM>>>(
        x_hi, x_lo, wq_hi, wq_lo, b_qkv, qkv, TOKENS, QKV_N, EMBED);

    // attention
    const int smemF = 4 * 64 * PAD * (int)sizeof(float);
    flash_attn<<<dim3(SEQ / 64, NHEAD, BATCH), 256, smemF>>>(qkv, attn);

    // split attention output
    {
        int n4 = TOKENS * EMBED / 4;
        split_kernel<<<(n4 + 255) / 256, 256>>>((const float4*)attn,
            (__nv_bfloat162*)at_hi, (__nv_bfloat162*)at_lo, n4);
    }

    // output projection
    gemm_hmma_x3<<<dim3(EMBED / 128, TOKENS / 128), 256, G_SMEM>>>(
        at_hi, at_lo, wp_hi, wp_lo, b_p, out, TOKENS, EMBED, EMBED);
}

// round 4
// speedup vs baseline: 2.7308x; 2.6923x over previous
#include <cuda_runtime.h>
#include <cuda_bf16.h>
#include <math.h>
#include <stdint.h>

#define EMBED   1024
#define NHEAD   16
#define HD      64
#define BATCH   2
#define SEQ     2048
#define TOKENS  (BATCH * SEQ)      // 4096
#define QKV_N   (3 * EMBED)        // 3072

// ---------------------------------------------------------------------------
// Scratch
// ---------------------------------------------------------------------------
__device__ float g_qkv [(size_t)TOKENS * QKV_N];
__device__ __nv_bfloat16 g_x_hi   [(size_t)TOKENS * EMBED];
__device__ __nv_bfloat16 g_x_lo   [(size_t)TOKENS * EMBED];
__device__ __nv_bfloat16 g_wqkv_hi[(size_t)QKV_N * EMBED];
__device__ __nv_bfloat16 g_wqkv_lo[(size_t)QKV_N * EMBED];
__device__ __nv_bfloat16 g_wp_hi  [(size_t)EMBED * EMBED];
__device__ __nv_bfloat16 g_wp_lo  [(size_t)EMBED * EMBED];
__device__ __nv_bfloat16 g_at_hi  [(size_t)TOKENS * EMBED];
__device__ __nv_bfloat16 g_at_lo  [(size_t)TOKENS * EMBED];
// per-head q/k/v hi/lo: [B*H][N][64]
#define HEADELEMS ((size_t)BATCH * NHEAD * SEQ * HD)
__device__ __nv_bfloat16 g_q_hi[HEADELEMS], g_q_lo[HEADELEMS];
__device__ __nv_bfloat16 g_k_hi[HEADELEMS], g_k_lo[HEADELEMS];
__device__ __nv_bfloat16 g_v_hi[HEADELEMS], g_v_lo[HEADELEMS];

// ---------------------------------------------------------------------------
// helpers
// ---------------------------------------------------------------------------
__device__ __forceinline__ uint32_t smem_u32(const void* p) {
    uint32_t a;
    asm("{ .reg .u64 t; cvta.to.shared.u64 t, %1; cvt.u32.u64 %0, t; }"
        : "=r"(a) : "l"(p));
    return a;
}
__device__ __forceinline__ void cp_async16(uint32_t s, const void* g) {
    asm volatile("cp.async.cg.shared.global [%0], [%1], 16;" :: "r"(s), "l"(g));
}
#define CP_COMMIT() asm volatile("cp.async.commit_group;" ::: "memory")
#define CP_WAIT1()  asm volatile("cp.async.wait_group 1;" ::: "memory")
#define CP_WAIT0()  asm volatile("cp.async.wait_group 0;" ::: "memory")

__device__ __forceinline__ void ldm_x4(uint32_t* r, uint32_t addr) {
    asm volatile("ldmatrix.sync.aligned.m8n8.x4.shared.b16 {%0,%1,%2,%3}, [%4];"
                 : "=r"(r[0]), "=r"(r[1]), "=r"(r[2]), "=r"(r[3]) : "r"(addr));
}
__device__ __forceinline__ void ldm_x4t(uint32_t* r, uint32_t addr) {
    asm volatile("ldmatrix.sync.aligned.m8n8.x4.trans.shared.b16 {%0,%1,%2,%3}, [%4];"
                 : "=r"(r[0]), "=r"(r[1]), "=r"(r[2]), "=r"(r[3]) : "r"(addr));
}
__device__ __forceinline__ void mma_bf16(float* c, const uint32_t* a,
                                         uint32_t b0, uint32_t b1) {
    asm volatile("mma.sync.aligned.m16n8k16.row.col.f32.bf16.bf16.f32 "
                 "{%0,%1,%2,%3}, {%4,%5,%6,%7}, {%8,%9}, {%0,%1,%2,%3};"
                 : "+f"(c[0]), "+f"(c[1]), "+f"(c[2]), "+f"(c[3])
                 : "r"(a[0]), "r"(a[1]), "r"(a[2]), "r"(a[3]), "r"(b0), "r"(b1));
}
__device__ __forceinline__ void split2(float x, float y, uint32_t& h, uint32_t& l) {
    __nv_bfloat16 hx = __float2bfloat16(x), hy = __float2bfloat16(y);
    __nv_bfloat16 lx = __float2bfloat16(x - __bfloat162float(hx));
    __nv_bfloat16 ly = __float2bfloat16(y - __bfloat162float(hy));
    __nv_bfloat162 hh = __halves2bfloat162(hx, hy), ll = __halves2bfloat162(lx, ly);
    h = *(uint32_t*)&hh; l = *(uint32_t*)&ll;
}

// ---------------------------------------------------------------------------
// fp32 -> bf16 hi/lo split
// ---------------------------------------------------------------------------
__global__ void split_kernel(const float4* __restrict__ in,
                             __nv_bfloat162* __restrict__ hi,
                             __nv_bfloat162* __restrict__ lo, int n4)
{
    int i = blockIdx.x * blockDim.x + threadIdx.x;
    if (i >= n4) return;
    float4 v = in[i];
    uint32_t h0, l0, h1, l1;
    split2(v.x, v.y, h0, l0);
    split2(v.z, v.w, h1, l1);
    ((uint32_t*)hi)[2 * i + 0] = h0; ((uint32_t*)hi)[2 * i + 1] = h1;
    ((uint32_t*)lo)[2 * i + 0] = l0; ((uint32_t*)lo)[2 * i + 1] = l1;
}

// ---------------------------------------------------------------------------
// qkv fp32 [token][3072] -> per-head hi/lo bf16 [bh][n][64]; Q scaled by 1/8
// ---------------------------------------------------------------------------
__global__ void qkv_extract(const float4* __restrict__ qkv)
{
    int i = blockIdx.x * blockDim.x + threadIdx.x;
    const int n4 = TOKENS * QKV_N / 4;
    if (i >= n4) return;
    int flat = i * 4;
    int token = flat / QKV_N;
    int j = flat - token * QKV_N;
    int t = j >> 10;
    int h = (j & 1023) >> 6;
    int d = j & 63;
    int b = token >> 11, n = token & 2047;
    size_t dst = (((size_t)(b * NHEAD + h) * SEQ) + n) * HD + d;

    float4 v = qkv[i];
    if (t == 0) { v.x *= 0.125f; v.y *= 0.125f; v.z *= 0.125f; v.w *= 0.125f; }
    uint32_t h0, l0, h1, l1;
    split2(v.x, v.y, h0, l0);
    split2(v.z, v.w, h1, l1);
    __nv_bfloat16 *dh, *dl;
    if (t == 0)      { dh = g_q_hi; dl = g_q_lo; }
    else if (t == 1) { dh = g_k_hi; dl = g_k_lo; }
    else             { dh = g_v_hi; dl = g_v_lo; }
    *(uint32_t*)(dh + dst)     = h0; *(uint32_t*)(dh + dst + 2) = h1;
    *(uint32_t*)(dl + dst)     = l0; *(uint32_t*)(dl + dst + 2) = l1;
}

// ---------------------------------------------------------------------------
// HMMA bf16x3 GEMM (unchanged from R3)
// ---------------------------------------------------------------------------
#define ROWB   80
#define TILE_B (128 * ROWB)
#define STG_B  (4 * TILE_B)
#define G_SMEM (2 * STG_B)

__global__ __launch_bounds__(256, 1)
void gemm_hmma_x3(const __nv_bfloat16* __restrict__ Ah, const __nv_bfloat16* __restrict__ Al,
                  const __nv_bfloat16* __restrict__ Bh, const __nv_bfloat16* __restrict__ Bl,
                  const float* __restrict__ bias, float* __restrict__ C,
                  int M, int N, int K)
{
    extern __shared__ char smem[];
    const uint32_t sb = smem_u32(smem);
    const int tid  = threadIdx.x;
    const int wid  = tid >> 5;
    const int lane = tid & 31;
    const int warp_m = wid & 1;
    const int warp_n = wid >> 1;
    const int m0 = blockIdx.y * 128;
    const int n0 = blockIdx.x * 128;

    const int lr = tid >> 2;
    const int lc = (tid & 3) * 16;

    const __nv_bfloat16* gA[4] = { Ah + (size_t)m0 * K, Al + (size_t)m0 * K,
                                   Bh + (size_t)n0 * K, Bl + (size_t)n0 * K };

    float acc[4][4][4];
#pragma unroll
    for (int i = 0; i < 4; i++)
#pragma unroll
        for (int j = 0; j < 4; j++)
#pragma unroll
            for (int f = 0; f < 4; f++) acc[i][j][f] = 0.0f;

    const int nk = K >> 5;

#pragma unroll
    for (int t = 0; t < 4; t++) {
        uint32_t sT = sb + t * TILE_B;
        cp_async16(sT + lr * ROWB + lc,        (const char*)(gA[t] + (size_t)lr * K) + lc);
        cp_async16(sT + (lr + 64) * ROWB + lc, (const char*)(gA[t] + (size_t)(lr + 64) * K) + lc);
    }
    CP_COMMIT();

    const uint32_t a_off = (uint32_t)(warp_m * 64 + (lane & 15)) * ROWB + (lane >> 4) * 16;
    const uint32_t b_off = (uint32_t)(warp_n * 32 + (lane & 15)) * ROWB + (lane >> 4) * 16;

    for (int c = 0; c < nk; c++) {
        const int buf = c & 1;
        if (c + 1 < nk) {
            const int kb = (c + 1) * 64;
#pragma unroll
            for (int t = 0; t < 4; t++) {
                uint32_t sT = sb + (buf ^ 1) * STG_B + t * TILE_B;
                cp_async16(sT + lr * ROWB + lc,        (const char*)(gA[t] + (size_t)lr * K) + kb + lc);
                cp_async16(sT + (lr + 64) * ROWB + lc, (const char*)(gA[t] + (size_t)(lr + 64) * K) + kb + lc);
            }
            CP_COMMIT();
            CP_WAIT1();
        } else {
            CP_WAIT0();
        }
        __syncthreads();

        const uint32_t st = sb + buf * STG_B;
#pragma unroll
        for (int ks = 0; ks < 2; ks++) {
            const uint32_t ko = ks * 32;
            uint32_t ah[4][4], al[4][4], bh[2][4], bl[2][4];
#pragma unroll
            for (int mt = 0; mt < 4; mt++) {
                ldm_x4(ah[mt], st + 0 * TILE_B + a_off + mt * 16 * ROWB + ko);
                ldm_x4(al[mt], st + 1 * TILE_B + a_off + mt * 16 * ROWB + ko);
            }
#pragma unroll
            for (int bt = 0; bt < 2; bt++) {
                ldm_x4(bh[bt], st + 2 * TILE_B + b_off + bt * 16 * ROWB + ko);
                ldm_x4(bl[bt], st + 3 * TILE_B + b_off + bt * 16 * ROWB + ko);
            }
#pragma unroll
            for (int mt = 0; mt < 4; mt++)
#pragma unroll
                for (int nt = 0; nt < 4; nt++) {
                    const int bt = nt >> 1, p = nt & 1;
                    mma_bf16(acc[mt][nt], ah[mt], bh[bt][p], bh[bt][p + 2]);
                    mma_bf16(acc[mt][nt], ah[mt], bl[bt][p], bl[bt][p + 2]);
                    mma_bf16(acc[mt][nt], al[mt], bh[bt][p], bh[bt][p + 2]);
                }
        }
        __syncthreads();
    }

    const int gr = lane >> 2;
    const int gc = (lane & 3) << 1;
#pragma unroll
    for (int mt = 0; mt < 4; mt++) {
        const int row = m0 + warp_m * 64 + mt * 16 + gr;
#pragma unroll
        for (int nt = 0; nt < 4; nt++) {
            const int col = n0 + warp_n * 32 + nt * 8 + gc;
            const float b0 = bias[col], b1 = bias[col + 1];
            float2 v0 = make_float2(acc[mt][nt][0] + b0, acc[mt][nt][1] + b1);
            float2 v1 = make_float2(acc[mt][nt][2] + b0, acc[mt][nt][3] + b1);
            *(float2*)(C + (size_t)row * N + col)       = v0;
            *(float2*)(C + (size_t)(row + 8) * N + col) = v1;
        }
    }
}

// ---------------------------------------------------------------------------
// HMMA flash attention, bf16x3 split, FA2-style register softmax.
// CTA: 128 queries of one (b,h); 8 warps, warp w owns rows 16w..16w+15.
// KV tiles of 64 keys, double-buffered cp.async.
// ---------------------------------------------------------------------------
#define BQ    128
#define BKV   64
#define KROWB 144                  // 64 bf16 = 128B + 16B pad
#define F_Q_H 0
#define F_Q_L (BQ * KROWB)         // 18432
#define F_KV  (2 * BQ * KROWB)     // 36864
#define F_T   (BKV * KROWB)        // 9216 per tensor
#define F_STG (4 * F_T)            // 36864 per stage
#define F_SMEM (F_KV + 2 * F_STG)  // 110592
#define NKV   (SEQ / BKV)          // 32

__global__ __launch_bounds__(256, 1)
void flash_hmma(const __nv_bfloat16* __restrict__ qh, const __nv_bfloat16* __restrict__ ql,
                const __nv_bfloat16* __restrict__ kh, const __nv_bfloat16* __restrict__ kl,
                const __nv_bfloat16* __restrict__ vh, const __nv_bfloat16* __restrict__ vl,
                __nv_bfloat16* __restrict__ oh, __nv_bfloat16* __restrict__ ol)
{
    extern __shared__ char smem[];
    const uint32_t sb = smem_u32(smem);
    const int tid = threadIdx.x;
    const int wid = tid >> 5;
    const int lane = tid & 31;

    const int q0 = blockIdx.x * BQ;
    const int h  = blockIdx.y;
    const int b  = blockIdx.z;
    const size_t hoff = ((size_t)(b * NHEAD + h)) * SEQ * HD;

    // ---- load Q hi/lo into smem (4 x 16B chunks per thread per tensor) ----
#pragma unroll
    for (int i = 0; i < 4; i++) {
        int chunk = tid + i * 256;           // 0..1023
        int row = chunk >> 3, col = (chunk & 7) * 16;
        cp_async16(sb + F_Q_H + row * KROWB + col,
                   (const char*)(qh + hoff + (size_t)(q0 + row) * HD) + col);
        cp_async16(sb + F_Q_L + row * KROWB + col,
                   (const char*)(ql + hoff + (size_t)(q0 + row) * HD) + col);
    }
    CP_COMMIT();

    // ---- preload KV tile 0 into stage 0 ----
#pragma unroll
    for (int i = 0; i < 2; i++) {
        int chunk = tid + i * 256;           // 0..511
        int row = chunk >> 3, col = (chunk & 7) * 16;
        uint32_t s = sb + F_KV + row * KROWB + col;
        const size_t g = hoff + (size_t)row * HD;
        cp_async16(s + 0 * F_T, (const char*)(kh + g) + col);
        cp_async16(s + 1 * F_T, (const char*)(kl + g) + col);
        cp_async16(s + 2 * F_T, (const char*)(vh + g) + col);
        cp_async16(s + 3 * F_T, (const char*)(vl + g) + col);
    }
    CP_COMMIT();

    CP_WAIT1();          // Q complete
    __syncthreads();

    // ---- Q fragments (held in registers all kernel) ----
    uint32_t qfh[4][4], qfl[4][4];
    {
        const uint32_t qa = sb + (uint32_t)(wid * 16 + (lane & 15)) * KROWB + 16 * (lane >> 4);
#pragma unroll
        for (int kt = 0; kt < 4; kt++) {
            ldm_x4(qfh[kt], qa + F_Q_H + kt * 32);
            ldm_x4(qfl[kt], qa + F_Q_L + kt * 32);
        }
    }

    float o[8][4];
#pragma unroll
    for (int nt = 0; nt < 8; nt++)
#pragma unroll
        for (int f = 0; f < 4; f++) o[nt][f] = 0.0f;
    float m0r = -INFINITY, m1r = -INFINITY, l0r = 0.0f, l1r = 0.0f;

    for (int t = 0; t < NKV; t++) {
        const int buf = t & 1;
        __syncthreads();   // everyone done reading buf^1 (overwritten below)
        if (t + 1 < NKV) {
            const int key0 = (t + 1) * BKV;
#pragma unroll
            for (int i = 0; i < 2; i++) {
                int chunk = tid + i * 256;
                int row = chunk >> 3, col = (chunk & 7) * 16;
                uint32_t s = sb + F_KV + (buf ^ 1) * F_STG + row * KROWB + col;
                const size_t g = hoff + (size_t)(key0 + row) * HD;
                cp_async16(s + 0 * F_T, (const char*)(kh + g) + col);
                cp_async16(s + 1 * F_T, (const char*)(kl + g) + col);
                cp_async16(s + 2 * F_T, (const char*)(vh + g) + col);
                cp_async16(s + 3 * F_T, (const char*)(vl + g) + col);
            }
            CP_COMMIT();
            CP_WAIT1();
        } else {
            CP_WAIT0();
        }
        __syncthreads();

        const uint32_t kvb = sb + F_KV + buf * F_STG;

        // ---- S = Qh Kh^T + Qh Kl^T + Ql Kh^T  (16 x 64 per warp) ----
        float s[8][4];
#pragma unroll
        for (int nt = 0; nt < 8; nt++)
#pragma unroll
            for (int f = 0; f < 4; f++) s[nt][f] = 0.0f;

#pragma unroll
        for (int ntp = 0; ntp < 4; ntp++) {
            const uint32_t ka = kvb + (uint32_t)(ntp * 16 + (lane & 15)) * KROWB + 16 * (lane >> 4);
#pragma unroll
            for (int kt = 0; kt < 4; kt++) {
                uint32_t kfh[4], kfl[4];
                ldm_x4(kfh, ka + 0 * F_T + kt * 32);
                ldm_x4(kfl, ka + 1 * F_T + kt * 32);
                mma_bf16(s[2 * ntp],     qfh[kt], kfh[0], kfh[2]);
                mma_bf16(s[2 * ntp],     qfh[kt], kfl[0], kfl[2]);
                mma_bf16(s[2 * ntp],     qfl[kt], kfh[0], kfh[2]);
                mma_bf16(s[2 * ntp + 1], qfh[kt], kfh[1], kfh[3]);
                mma_bf16(s[2 * ntp + 1], qfh[kt], kfl[1], kfl[3]);
                mma_bf16(s[2 * ntp + 1], qfl[kt], kfh[1], kfh[3]);
            }
        }

        // ---- online softmax (rows r = lane>>2 and r+8) ----
        float mx0 = -INFINITY, mx1 = -INFINITY;
#pragma unroll
        for (int nt = 0; nt < 8; nt++) {
            mx0 = fmaxf(mx0, fmaxf(s[nt][0], s[nt][1]));
            mx1 = fmaxf(mx1, fmaxf(s[nt][2], s[nt][3]));
        }
        mx0 = fmaxf(mx0, __shfl_xor_sync(0xffffffffu, mx0, 1));
        mx0 = fmaxf(mx0, __shfl_xor_sync(0xffffffffu, mx0, 2));
        mx1 = fmaxf(mx1, __shfl_xor_sync(0xffffffffu, mx1, 1));
        mx1 = fmaxf(mx1, __shfl_xor_sync(0xffffffffu, mx1, 2));

        const float mn0 = fmaxf(m0r, mx0), mn1 = fmaxf(m1r, mx1);
        const float a0 = __expf(m0r - mn0), a1 = __expf(m1r - mn1);
        m0r = mn0; m1r = mn1;

        float rs0 = 0.0f, rs1 = 0.0f;
#pragma unroll
        for (int nt = 0; nt < 8; nt++) {
            s[nt][0] = __expf(s[nt][0] - mn0); s[nt][1] = __expf(s[nt][1] - mn0);
            s[nt][2] = __expf(s[nt][2] - mn1); s[nt][3] = __expf(s[nt][3] - mn1);
            rs0 += s[nt][0] + s[nt][1];
            rs1 += s[nt][2] + s[nt][3];
        }
        rs0 += __shfl_xor_sync(0xffffffffu, rs0, 1);
        rs0 += __shfl_xor_sync(0xffffffffu, rs0, 2);
        rs1 += __shfl_xor_sync(0xffffffffu, rs1, 1);
        rs1 += __shfl_xor_sync(0xffffffffu, rs1, 2);
        l0r = l0r * a0 + rs0;
        l1r = l1r * a1 + rs1;

#pragma unroll
        for (int nt = 0; nt < 8; nt++) {
            o[nt][0] *= a0; o[nt][1] *= a0;
            o[nt][2] *= a1; o[nt][3] *= a1;
        }

        // ---- O += Ph Vh + Pl Vh + Ph Vl ----
#pragma unroll
        for (int kt = 0; kt < 4; kt++) {
            // pack P A-fragments from S C-fragments (n-tiles 2kt, 2kt+1)
            uint32_t ph[4], pl[4];
            split2(s[2 * kt][0],     s[2 * kt][1],     ph[0], pl[0]);
            split2(s[2 * kt][2],     s[2 * kt][3],     ph[1], pl[1]);
            split2(s[2 * kt + 1][0], s[2 * kt + 1][1], ph[2], pl[2]);
            split2(s[2 * kt + 1][2], s[2 * kt + 1][3], ph[3], pl[3]);

            const uint32_t va = kvb + (uint32_t)(kt * 16 + (lane & 15)) * KROWB + 16 * (lane >> 4);
#pragma unroll
            for (int ntp = 0; ntp < 4; ntp++) {
                uint32_t vfh[4], vfl[4];
                ldm_x4t(vfh, va + 2 * F_T + ntp * 32);
                ldm_x4t(vfl, va + 3 * F_T + ntp * 32);
                mma_bf16(o[2 * ntp],     ph, vfh[0], vfh[1]);
                mma_bf16(o[2 * ntp],     pl, vfh[0], vfh[1]);
                mma_bf16(o[2 * ntp],     ph, vfl[0], vfl[1]);
                mma_bf16(o[2 * ntp + 1], ph, vfh[2], vfh[3]);
                mma_bf16(o[2 * ntp + 1], pl, vfh[2], vfh[3]);
                mma_bf16(o[2 * ntp + 1], ph, vfl[2], vfl[3]);
            }
        }
    }

    // ---- epilogue: O/l -> bf16 hi/lo at [token][h*64+d] ----
    const float inv0 = 1.0f / l0r, inv1 = 1.0f / l1r;
    const int gr = lane >> 2, gc = (lane & 3) * 2;
    const size_t row0 = (size_t)(b * SEQ + q0 + wid * 16 + gr) * EMBED + h * HD;
    const size_t row1 = row0 + 8 * EMBED;
#pragma unroll
    for (int nt = 0; nt < 8; nt++) {
        const int d = nt * 8 + gc;
        uint32_t hh, ll;
        split2(o[nt][0] * inv0, o[nt][1] * inv0, hh, ll);
        *(uint32_t*)(oh + row0 + d) = hh;
        *(uint32_t*)(ol + row0 + d) = ll;
        split2(o[nt][2] * inv1, o[nt][3] * inv1, hh, ll);
        *(uint32_t*)(oh + row1 + d) = hh;
        *(uint32_t*)(ol + row1 + d) = ll;
    }
}

// ---------------------------------------------------------------------------
extern "C" void kernel_launch(void* const* d_in, const int* in_sizes, int n_in,
                              void* d_out, int out_size)
{
    const float* x     = (const float*)d_in[0];
    const float* W_qkv = (const float*)d_in[1];
    const float* b_qkv = (const float*)d_in[2];
    const float* W_p   = (const float*)d_in[3];
    const float* b_p   = (const float*)d_in[4];
    float* out = (float*)d_out;

    float* qkv;
    __nv_bfloat16 *x_hi, *x_lo, *wq_hi, *wq_lo, *wp_hi, *wp_lo, *at_hi, *at_lo;
    __nv_bfloat16 *q_hi, *q_lo, *k_hi, *k_lo, *v_hi, *v_lo;
    cudaGetSymbolAddress((void**)&qkv,   g_qkv);
    cudaGetSymbolAddress((void**)&x_hi,  g_x_hi);
    cudaGetSymbolAddress((void**)&x_lo,  g_x_lo);
    cudaGetSymbolAddress((void**)&wq_hi, g_wqkv_hi);
    cudaGetSymbolAddress((void**)&wq_lo, g_wqkv_lo);
    cudaGetSymbolAddress((void**)&wp_hi, g_wp_hi);
    cudaGetSymbolAddress((void**)&wp_lo, g_wp_lo);
    cudaGetSymbolAddress((void**)&at_hi, g_at_hi);
    cudaGetSymbolAddress((void**)&at_lo, g_at_lo);
    cudaGetSymbolAddress((void**)&q_hi,  g_q_hi);
    cudaGetSymbolAddress((void**)&q_lo,  g_q_lo);
    cudaGetSymbolAddress((void**)&k_hi,  g_k_hi);
    cudaGetSymbolAddress((void**)&k_lo,  g_k_lo);
    cudaGetSymbolAddress((void**)&v_hi,  g_v_hi);
    cudaGetSymbolAddress((void**)&v_lo,  g_v_lo);

    cudaFuncSetAttribute(gemm_hmma_x3, cudaFuncAttributeMaxDynamicSharedMemorySize, G_SMEM);
    cudaFuncSetAttribute(flash_hmma,   cudaFuncAttributeMaxDynamicSharedMemorySize, F_SMEM);

    // input splits
    {
        int n4 = TOKENS * EMBED / 4;
        split_kernel<<<(n4 + 255) / 256, 256>>>((const float4*)x,
            (__nv_bfloat162*)x_hi, (__nv_bfloat162*)x_lo, n4);
    }
    {
        int n4 = QKV_N * EMBED / 4;
        split_kernel<<<(n4 + 255) / 256, 256>>>((const float4*)W_qkv,
            (__nv_bfloat162*)wq_hi, (__nv_bfloat162*)wq_lo, n4);
    }
    {
        int n4 = EMBED * EMBED / 4;
        split_kernel<<<(n4 + 255) / 256, 256>>>((const float4*)W_p,
            (__nv_bfloat162*)wp_hi, (__nv_bfloat162*)wp_lo, n4);
    }

    // QKV projection
    gemm_hmma_x3<<<dim3(QKV_N / 128, TOKENS / 128), 256, G_SMEM>>>(
        x_hi, x_lo, wq_hi, wq_lo, b_qkv, qkv, TOKENS, QKV_N, EMBED);

    // extract per-head bf16 hi/lo q/k/v (q scaled by 1/8)
    {
        int n4 = TOKENS * QKV_N / 4;
        qkv_extract<<<(n4 + 255) / 256, 256>>>((const float4*)qkv);
    }

    // attention (HMMA flash) -> at_hi/at_lo
    flash_hmma<<<dim3(SEQ / BQ, NHEAD, BATCH), 256, F_SMEM>>>(
        q_hi, q_lo, k_hi, k_lo, v_hi, v_lo, at_hi, at_lo);

    // output projection
    gemm_hmma_x3<<<dim3(EMBED / 128, TOKENS / 128), 256, G_SMEM>>>(
        at_hi, at_lo, wp_hi, wp_lo, b_p, out, TOKENS, EMBED, EMBED);
}

// round 5
// speedup vs baseline: 2.8060x; 1.0276x over previous
#include <cuda_runtime.h>
#include <cuda_bf16.h>
#include <math.h>
#include <stdint.h>

#define EMBED   1024
#define NHEAD   16
#define HD      64
#define BATCH   2
#define SEQ     2048
#define TOKENS  (BATCH * SEQ)      // 4096
#define QKV_N   (3 * EMBED)        // 3072

// ---------------------------------------------------------------------------
// Scratch
// ---------------------------------------------------------------------------
__device__ __nv_bfloat16 g_x_hi   [(size_t)TOKENS * EMBED];
__device__ __nv_bfloat16 g_x_lo   [(size_t)TOKENS * EMBED];
__device__ __nv_bfloat16 g_wqkv_hi[(size_t)QKV_N * EMBED];
__device__ __nv_bfloat16 g_wqkv_lo[(size_t)QKV_N * EMBED];
__device__ __nv_bfloat16 g_wp_hi  [(size_t)EMBED * EMBED];
__device__ __nv_bfloat16 g_wp_lo  [(size_t)EMBED * EMBED];
__device__ __nv_bfloat16 g_at_hi  [(size_t)TOKENS * EMBED];
__device__ __nv_bfloat16 g_at_lo  [(size_t)TOKENS * EMBED];
#define HEADELEMS ((size_t)BATCH * NHEAD * SEQ * HD)
__device__ __nv_bfloat16 g_q_hi[HEADELEMS], g_q_lo[HEADELEMS];
__device__ __nv_bfloat16 g_k_hi[HEADELEMS], g_k_lo[HEADELEMS];
__device__ __nv_bfloat16 g_v_hi[HEADELEMS], g_v_lo[HEADELEMS];

// ---------------------------------------------------------------------------
// helpers
// ---------------------------------------------------------------------------
__device__ __forceinline__ uint32_t smem_u32(const void* p) {
    uint32_t a;
    asm("{ .reg .u64 t; cvta.to.shared.u64 t, %1; cvt.u32.u64 %0, t; }"
        : "=r"(a) : "l"(p));
    return a;
}
__device__ __forceinline__ void cp_async16(uint32_t s, const void* g) {
    asm volatile("cp.async.cg.shared.global [%0], [%1], 16;" :: "r"(s), "l"(g));
}
#define CP_COMMIT() asm volatile("cp.async.commit_group;" ::: "memory")
#define CP_WAIT1()  asm volatile("cp.async.wait_group 1;" ::: "memory")
#define CP_WAIT0()  asm volatile("cp.async.wait_group 0;" ::: "memory")

__device__ __forceinline__ void ldm_x4(uint32_t* r, uint32_t addr) {
    asm volatile("ldmatrix.sync.aligned.m8n8.x4.shared.b16 {%0,%1,%2,%3}, [%4];"
                 : "=r"(r[0]), "=r"(r[1]), "=r"(r[2]), "=r"(r[3]) : "r"(addr));
}
__device__ __forceinline__ void ldm_x4t(uint32_t* r, uint32_t addr) {
    asm volatile("ldmatrix.sync.aligned.m8n8.x4.trans.shared.b16 {%0,%1,%2,%3}, [%4];"
                 : "=r"(r[0]), "=r"(r[1]), "=r"(r[2]), "=r"(r[3]) : "r"(addr));
}
__device__ __forceinline__ void mma_bf16(float* c, const uint32_t* a,
                                         uint32_t b0, uint32_t b1) {
    asm volatile("mma.sync.aligned.m16n8k16.row.col.f32.bf16.bf16.f32 "
                 "{%0,%1,%2,%3}, {%4,%5,%6,%7}, {%8,%9}, {%0,%1,%2,%3};"
                 : "+f"(c[0]), "+f"(c[1]), "+f"(c[2]), "+f"(c[3])
                 : "r"(a[0]), "r"(a[1]), "r"(a[2]), "r"(a[3]), "r"(b0), "r"(b1));
}
__device__ __forceinline__ void split2(float x, float y, uint32_t& h, uint32_t& l) {
    __nv_bfloat16 hx = __float2bfloat16(x), hy = __float2bfloat16(y);
    __nv_bfloat16 lx = __float2bfloat16(x - __bfloat162float(hx));
    __nv_bfloat16 ly = __float2bfloat16(y - __bfloat162float(hy));
    __nv_bfloat162 hh = __halves2bfloat162(hx, hy), ll = __halves2bfloat162(lx, ly);
    h = *(uint32_t*)&hh; l = *(uint32_t*)&ll;
}

// ---------------------------------------------------------------------------
// fp32 -> bf16 hi/lo split
// ---------------------------------------------------------------------------
__global__ void split_kernel(const float4* __restrict__ in,
                             __nv_bfloat162* __restrict__ hi,
                             __nv_bfloat162* __restrict__ lo, int n4)
{
    int i = blockIdx.x * blockDim.x + threadIdx.x;
    if (i >= n4) return;
    float4 v = in[i];
    uint32_t h0, l0, h1, l1;
    split2(v.x, v.y, h0, l0);
    split2(v.z, v.w, h1, l1);
    ((uint32_t*)hi)[2 * i + 0] = h0; ((uint32_t*)hi)[2 * i + 1] = h1;
    ((uint32_t*)lo)[2 * i + 0] = l0; ((uint32_t*)lo)[2 * i + 1] = l1;
}

// ---------------------------------------------------------------------------
// HMMA bf16x3 GEMM. MODE 0: fp32 C + bias. MODE 1: QKV — split to per-head
// bf16 hi/lo q/k/v buffers (Q scaled by 1/8), C unused.
// ---------------------------------------------------------------------------
#define ROWB   80
#define TILE_B (128 * ROWB)
#define STG_B  (4 * TILE_B)
#define G_SMEM (2 * STG_B)    // 81920

template <int MODE>
__global__ __launch_bounds__(256, 2)
void gemm_hmma_x3(const __nv_bfloat16* __restrict__ Ah, const __nv_bfloat16* __restrict__ Al,
                  const __nv_bfloat16* __restrict__ Bh, const __nv_bfloat16* __restrict__ Bl,
                  const float* __restrict__ bias, float* __restrict__ C,
                  int M, int N, int K)
{
    extern __shared__ char smem[];
    const uint32_t sb = smem_u32(smem);
    const int tid  = threadIdx.x;
    const int wid  = tid >> 5;
    const int lane = tid & 31;
    const int warp_m = wid & 1;
    const int warp_n = wid >> 1;
    const int m0 = blockIdx.y * 128;
    const int n0 = blockIdx.x * 128;

    const int lr = tid >> 2;
    const int lc = (tid & 3) * 16;

    const __nv_bfloat16* gA[4] = { Ah + (size_t)m0 * K, Al + (size_t)m0 * K,
                                   Bh + (size_t)n0 * K, Bl + (size_t)n0 * K };

    float acc[4][4][4];
#pragma unroll
    for (int i = 0; i < 4; i++)
#pragma unroll
        for (int j = 0; j < 4; j++)
#pragma unroll
            for (int f = 0; f < 4; f++) acc[i][j][f] = 0.0f;

    const int nk = K >> 5;

#pragma unroll
    for (int t = 0; t < 4; t++) {
        uint32_t sT = sb + t * TILE_B;
        cp_async16(sT + lr * ROWB + lc,        (const char*)(gA[t] + (size_t)lr * K) + lc);
        cp_async16(sT + (lr + 64) * ROWB + lc, (const char*)(gA[t] + (size_t)(lr + 64) * K) + lc);
    }
    CP_COMMIT();

    const uint32_t a_off = (uint32_t)(warp_m * 64 + (lane & 15)) * ROWB + (lane >> 4) * 16;
    const uint32_t b_off = (uint32_t)(warp_n * 32 + (lane & 15)) * ROWB + (lane >> 4) * 16;

    for (int c = 0; c < nk; c++) {
        const int buf = c & 1;
        if (c + 1 < nk) {
            const int kb = (c + 1) * 64;
#pragma unroll
            for (int t = 0; t < 4; t++) {
                uint32_t sT = sb + (buf ^ 1) * STG_B + t * TILE_B;
                cp_async16(sT + lr * ROWB + lc,        (const char*)(gA[t] + (size_t)lr * K) + kb + lc);
                cp_async16(sT + (lr + 64) * ROWB + lc, (const char*)(gA[t] + (size_t)(lr + 64) * K) + kb + lc);
            }
            CP_COMMIT();
            CP_WAIT1();
        } else {
            CP_WAIT0();
        }
        __syncthreads();

        const uint32_t st = sb + buf * STG_B;
#pragma unroll
        for (int ks = 0; ks < 2; ks++) {
            const uint32_t ko = ks * 32;
            uint32_t ah[4][4], al[4][4], bh[2][4], bl[2][4];
#pragma unroll
            for (int mt = 0; mt < 4; mt++) {
                ldm_x4(ah[mt], st + 0 * TILE_B + a_off + mt * 16 * ROWB + ko);
                ldm_x4(al[mt], st + 1 * TILE_B + a_off + mt * 16 * ROWB + ko);
            }
#pragma unroll
            for (int bt = 0; bt < 2; bt++) {
                ldm_x4(bh[bt], st + 2 * TILE_B + b_off + bt * 16 * ROWB + ko);
                ldm_x4(bl[bt], st + 3 * TILE_B + b_off + bt * 16 * ROWB + ko);
            }
#pragma unroll
            for (int mt = 0; mt < 4; mt++)
#pragma unroll
                for (int nt = 0; nt < 4; nt++) {
                    const int bt = nt >> 1, p = nt & 1;
                    mma_bf16(acc[mt][nt], ah[mt], bh[bt][p], bh[bt][p + 2]);
                    mma_bf16(acc[mt][nt], ah[mt], bl[bt][p], bl[bt][p + 2]);
                    mma_bf16(acc[mt][nt], al[mt], bh[bt][p], bh[bt][p + 2]);
                }
        }
        __syncthreads();
    }

    const int gr = lane >> 2;
    const int gc = (lane & 3) << 1;
#pragma unroll
    for (int mt = 0; mt < 4; mt++) {
        const int row = m0 + warp_m * 64 + mt * 16 + gr;
#pragma unroll
        for (int nt = 0; nt < 4; nt++) {
            const int col = n0 + warp_n * 32 + nt * 8 + gc;
            const float b0 = bias[col], b1 = bias[col + 1];
            float x0 = acc[mt][nt][0] + b0, x1 = acc[mt][nt][1] + b1;
            float y0 = acc[mt][nt][2] + b0, y1 = acc[mt][nt][3] + b1;
            if (MODE == 0) {
                *(float2*)(C + (size_t)row * N + col)       = make_float2(x0, x1);
                *(float2*)(C + (size_t)(row + 8) * N + col) = make_float2(y0, y1);
            } else {
                const int t = col >> 10;             // 0=q 1=k 2=v
                const int h = (col >> 6) & (NHEAD - 1);
                const int d = col & (HD - 1);
                const int bb = row >> 11, sq = row & (SEQ - 1);
                const size_t dst = (((size_t)(bb * NHEAD + h) * SEQ) + sq) * HD + d;
                if (t == 0) { x0 *= 0.125f; x1 *= 0.125f; y0 *= 0.125f; y1 *= 0.125f; }
                __nv_bfloat16 *dh, *dl;
                if (t == 0)      { dh = g_q_hi; dl = g_q_lo; }
                else if (t == 1) { dh = g_k_hi; dl = g_k_lo; }
                else             { dh = g_v_hi; dl = g_v_lo; }
                uint32_t hh, ll;
                split2(x0, x1, hh, ll);
                *(uint32_t*)(dh + dst) = hh;
                *(uint32_t*)(dl + dst) = ll;
                split2(y0, y1, hh, ll);
                *(uint32_t*)(dh + dst + 8 * HD) = hh;
                *(uint32_t*)(dl + dst + 8 * HD) = ll;
            }
        }
    }
}

// ---------------------------------------------------------------------------
// HMMA flash attention. Q smem region is reused as KV stage 1 after the Q
// fragments move to registers -> smem 72KB -> 2 CTAs/SM.
// ---------------------------------------------------------------------------
#define BQ    128
#define BKV   64
#define KROWB 144
#define F_T   (BKV * KROWB)        // 9216
#define F_STG (4 * F_T)            // 36864 (== Q hi+lo region size)
#define F_SMEM (2 * F_STG)         // 73728
#define NKV   (SEQ / BKV)          // 32

__global__ __launch_bounds__(256, 2)
void flash_hmma(const __nv_bfloat16* __restrict__ qh, const __nv_bfloat16* __restrict__ ql,
                const __nv_bfloat16* __restrict__ kh, const __nv_bfloat16* __restrict__ kl,
                const __nv_bfloat16* __restrict__ vh, const __nv_bfloat16* __restrict__ vl,
                __nv_bfloat16* __restrict__ oh, __nv_bfloat16* __restrict__ ol)
{
    extern __shared__ char smem[];
    const uint32_t sb = smem_u32(smem);
    const int tid = threadIdx.x;
    const int wid = tid >> 5;
    const int lane = tid & 31;

    const int q0 = blockIdx.x * BQ;
    const int h  = blockIdx.y;
    const int b  = blockIdx.z;
    const size_t hoff = ((size_t)(b * NHEAD + h)) * SEQ * HD;

    // Q hi/lo -> smem region [0, F_STG)  (hi at 0, lo at 2*F_T)
#pragma unroll
    for (int i = 0; i < 4; i++) {
        int chunk = tid + i * 256;           // 0..1023
        int row = chunk >> 3, col = (chunk & 7) * 16;
        cp_async16(sb + row * KROWB + col,
                   (const char*)(qh + hoff + (size_t)(q0 + row) * HD) + col);
        cp_async16(sb + 2 * F_T + row * KROWB + col,
                   (const char*)(ql + hoff + (size_t)(q0 + row) * HD) + col);
    }
    CP_COMMIT();

    // KV tile 0 -> stage at F_STG
#pragma unroll
    for (int i = 0; i < 2; i++) {
        int chunk = tid + i * 256;
        int row = chunk >> 3, col = (chunk & 7) * 16;
        uint32_t s = sb + F_STG + row * KROWB + col;
        const size_t g = hoff + (size_t)row * HD;
        cp_async16(s + 0 * F_T, (const char*)(kh + g) + col);
        cp_async16(s + 1 * F_T, (const char*)(kl + g) + col);
        cp_async16(s + 2 * F_T, (const char*)(vh + g) + col);
        cp_async16(s + 3 * F_T, (const char*)(vl + g) + col);
    }
    CP_COMMIT();

    CP_WAIT1();          // Q done
    __syncthreads();

    uint32_t qfh[4][4], qfl[4][4];
    {
        const uint32_t qa = sb + (uint32_t)(wid * 16 + (lane & 15)) * KROWB + 16 * (lane >> 4);
#pragma unroll
        for (int kt = 0; kt < 4; kt++) {
            ldm_x4(qfh[kt], qa + kt * 32);
            ldm_x4(qfl[kt], qa + 2 * F_T + kt * 32);
        }
    }

    float o[8][4];
#pragma unroll
    for (int nt = 0; nt < 8; nt++)
#pragma unroll
        for (int f = 0; f < 4; f++) o[nt][f] = 0.0f;
    float m0r = -INFINITY, m1r = -INFINITY, l0r = 0.0f, l1r = 0.0f;

    for (int t = 0; t < NKV; t++) {
        // stage(t): even -> F_STG, odd -> 0 (Q region, dead after frag load)
        const uint32_t kvb = sb + ((t & 1) ? 0 : F_STG);
        __syncthreads();   // all warps done with the buffer we're about to fill
        if (t + 1 < NKV) {
            const uint32_t dstb = sb + (((t + 1) & 1) ? 0 : F_STG);
            const int key0 = (t + 1) * BKV;
#pragma unroll
            for (int i = 0; i < 2; i++) {
                int chunk = tid + i * 256;
                int row = chunk >> 3, col = (chunk & 7) * 16;
                uint32_t s = dstb + row * KROWB + col;
                const size_t g = hoff + (size_t)(key0 + row) * HD;
                cp_async16(s + 0 * F_T, (const char*)(kh + g) + col);
                cp_async16(s + 1 * F_T, (const char*)(kl + g) + col);
                cp_async16(s + 2 * F_T, (const char*)(vh + g) + col);
                cp_async16(s + 3 * F_T, (const char*)(vl + g) + col);
            }
            CP_COMMIT();
            CP_WAIT1();
        } else {
            CP_WAIT0();
        }
        __syncthreads();

        // S = Qh Kh^T + Qh Kl^T + Ql Kh^T
        float s[8][4];
#pragma unroll
        for (int nt = 0; nt < 8; nt++)
#pragma unroll
            for (int f = 0; f < 4; f++) s[nt][f] = 0.0f;

#pragma unroll
        for (int ntp = 0; ntp < 4; ntp++) {
            const uint32_t ka = kvb + (uint32_t)(ntp * 16 + (lane & 15)) * KROWB + 16 * (lane >> 4);
#pragma unroll
            for (int kt = 0; kt < 4; kt++) {
                uint32_t kfh[4], kfl[4];
                ldm_x4(kfh, ka + 0 * F_T + kt * 32);
                ldm_x4(kfl, ka + 1 * F_T + kt * 32);
                mma_bf16(s[2 * ntp],     qfh[kt], kfh[0], kfh[2]);
                mma_bf16(s[2 * ntp],     qfh[kt], kfl[0], kfl[2]);
                mma_bf16(s[2 * ntp],     qfl[kt], kfh[0], kfh[2]);
                mma_bf16(s[2 * ntp + 1], qfh[kt], kfh[1], kfh[3]);
                mma_bf16(s[2 * ntp + 1], qfh[kt], kfl[1], kfl[3]);
                mma_bf16(s[2 * ntp + 1], qfl[kt], kfh[1], kfh[3]);
            }
        }

        // online softmax
        float mx0 = -INFINITY, mx1 = -INFINITY;
#pragma unroll
        for (int nt = 0; nt < 8; nt++) {
            mx0 = fmaxf(mx0, fmaxf(s[nt][0], s[nt][1]));
            mx1 = fmaxf(mx1, fmaxf(s[nt][2], s[nt][3]));
        }
        mx0 = fmaxf(mx0, __shfl_xor_sync(0xffffffffu, mx0, 1));
        mx0 = fmaxf(mx0, __shfl_xor_sync(0xffffffffu, mx0, 2));
        mx1 = fmaxf(mx1, __shfl_xor_sync(0xffffffffu, mx1, 1));
        mx1 = fmaxf(mx1, __shfl_xor_sync(0xffffffffu, mx1, 2));

        const float mn0 = fmaxf(m0r, mx0), mn1 = fmaxf(m1r, mx1);
        const float a0 = __expf(m0r - mn0), a1 = __expf(m1r - mn1);
        m0r = mn0; m1r = mn1;

        float rs0 = 0.0f, rs1 = 0.0f;
#pragma unroll
        for (int nt = 0; nt < 8; nt++) {
            s[nt][0] = __expf(s[nt][0] - mn0); s[nt][1] = __expf(s[nt][1] - mn0);
            s[nt][2] = __expf(s[nt][2] - mn1); s[nt][3] = __expf(s[nt][3] - mn1);
            rs0 += s[nt][0] + s[nt][1];
            rs1 += s[nt][2] + s[nt][3];
        }
        rs0 += __shfl_xor_sync(0xffffffffu, rs0, 1);
        rs0 += __shfl_xor_sync(0xffffffffu, rs0, 2);
        rs1 += __shfl_xor_sync(0xffffffffu, rs1, 1);
        rs1 += __shfl_xor_sync(0xffffffffu, rs1, 2);
        l0r = l0r * a0 + rs0;
        l1r = l1r * a1 + rs1;

#pragma unroll
        for (int nt = 0; nt < 8; nt++) {
            o[nt][0] *= a0; o[nt][1] *= a0;
            o[nt][2] *= a1; o[nt][3] *= a1;
        }

        // O += Ph Vh + Pl Vh + Ph Vl
#pragma unroll
        for (int kt = 0; kt < 4; kt++) {
            uint32_t ph[4], pl[4];
            split2(s[2 * kt][0],     s[2 * kt][1],     ph[0], pl[0]);
            split2(s[2 * kt][2],     s[2 * kt][3],     ph[1], pl[1]);
            split2(s[2 * kt + 1][0], s[2 * kt + 1][1], ph[2], pl[2]);
            split2(s[2 * kt + 1][2], s[2 * kt + 1][3], ph[3], pl[3]);

            const uint32_t va = kvb + (uint32_t)(kt * 16 + (lane & 15)) * KROWB + 16 * (lane >> 4);
#pragma unroll
            for (int ntp = 0; ntp < 4; ntp++) {
                uint32_t vfh[4], vfl[4];
                ldm_x4t(vfh, va + 2 * F_T + ntp * 32);
                ldm_x4t(vfl, va + 3 * F_T + ntp * 32);
                mma_bf16(o[2 * ntp],     ph, vfh[0], vfh[1]);
                mma_bf16(o[2 * ntp],     pl, vfh[0], vfh[1]);
                mma_bf16(o[2 * ntp],     ph, vfl[0], vfl[1]);
                mma_bf16(o[2 * ntp + 1], ph, vfh[2], vfh[3]);
                mma_bf16(o[2 * ntp + 1], pl, vfh[2], vfh[3]);
                mma_bf16(o[2 * ntp + 1], ph, vfl[2], vfl[3]);
            }
        }
    }

    const float inv0 = 1.0f / l0r, inv1 = 1.0f / l1r;
    const int gr = lane >> 2, gc = (lane & 3) * 2;
    const size_t row0 = (size_t)(b * SEQ + q0 + wid * 16 + gr) * EMBED + h * HD;
    const size_t row1 = row0 + 8 * EMBED;
#pragma unroll
    for (int nt = 0; nt < 8; nt++) {
        const int d = nt * 8 + gc;
        uint32_t hh, ll;
        split2(o[nt][0] * inv0, o[nt][1] * inv0, hh, ll);
        *(uint32_t*)(oh + row0 + d) = hh;
        *(uint32_t*)(ol + row0 + d) = ll;
        split2(o[nt][2] * inv1, o[nt][3] * inv1, hh, ll);
        *(uint32_t*)(oh + row1 + d) = hh;
        *(uint32_t*)(ol + row1 + d) = ll;
    }
}

// ---------------------------------------------------------------------------
extern "C" void kernel_launch(void* const* d_in, const int* in_sizes, int n_in,
                              void* d_out, int out_size)
{
    const float* x     = (const float*)d_in[0];
    const float* W_qkv = (const float*)d_in[1];
    const float* b_qkv = (const float*)d_in[2];
    const float* W_p   = (const float*)d_in[3];
    const float* b_p   = (const float*)d_in[4];
    float* out = (float*)d_out;

    __nv_bfloat16 *x_hi, *x_lo, *wq_hi, *wq_lo, *wp_hi, *wp_lo, *at_hi, *at_lo;
    __nv_bfloat16 *q_hi, *q_lo, *k_hi, *k_lo, *v_hi, *v_lo;
    cudaGetSymbolAddress((void**)&x_hi,  g_x_hi);
    cudaGetSymbolAddress((void**)&x_lo,  g_x_lo);
    cudaGetSymbolAddress((void**)&wq_hi, g_wqkv_hi);
    cudaGetSymbolAddress((void**)&wq_lo, g_wqkv_lo);
    cudaGetSymbolAddress((void**)&wp_hi, g_wp_hi);
    cudaGetSymbolAddress((void**)&wp_lo, g_wp_lo);
    cudaGetSymbolAddress((void**)&at_hi, g_at_hi);
    cudaGetSymbolAddress((void**)&at_lo, g_at_lo);
    cudaGetSymbolAddress((void**)&q_hi,  g_q_hi);
    cudaGetSymbolAddress((void**)&q_lo,  g_q_lo);
    cudaGetSymbolAddress((void**)&k_hi,  g_k_hi);
    cudaGetSymbolAddress((void**)&k_lo,  g_k_lo);
    cudaGetSymbolAddress((void**)&v_hi,  g_v_hi);
    cudaGetSymbolAddress((void**)&v_lo,  g_v_lo);

    cudaFuncSetAttribute(gemm_hmma_x3<0>, cudaFuncAttributeMaxDynamicSharedMemorySize, G_SMEM);
    cudaFuncSetAttribute(gemm_hmma_x3<1>, cudaFuncAttributeMaxDynamicSharedMemorySize, G_SMEM);
    cudaFuncSetAttribute(flash_hmma,      cudaFuncAttributeMaxDynamicSharedMemorySize, F_SMEM);

    // input splits
    {
        int n4 = TOKENS * EMBED / 4;
        split_kernel<<<(n4 + 255) / 256, 256>>>((const float4*)x,
            (__nv_bfloat162*)x_hi, (__nv_bfloat162*)x_lo, n4);
    }
    {
        int n4 = QKV_N * EMBED / 4;
        split_kernel<<<(n4 + 255) / 256, 256>>>((const float4*)W_qkv,
            (__nv_bfloat162*)wq_hi, (__nv_bfloat162*)wq_lo, n4);
    }
    {
        int n4 = EMBED * EMBED / 4;
        split_kernel<<<(n4 + 255) / 256, 256>>>((const float4*)W_p,
            (__nv_bfloat162*)wp_hi, (__nv_bfloat162*)wp_lo, n4);
    }

    // QKV projection: epilogue writes per-head q/k/v hi/lo directly
    gemm_hmma_x3<1><<<dim3(QKV_N / 128, TOKENS / 128), 256, G_SMEM>>>(
        x_hi, x_lo, wq_hi, wq_lo, b_qkv, nullptr, TOKENS, QKV_N, EMBED);

    // attention
    flash_hmma<<<dim3(SEQ / BQ, NHEAD, BATCH), 256, F_SMEM>>>(
        q_hi, q_lo, k_hi, k_lo, v_hi, v_lo, at_hi, at_lo);

    // output projection
    gemm_hmma_x3<0><<<dim3(EMBED / 128, TOKENS / 128), 256, G_SMEM>>>(
        at_hi, at_lo, wp_hi, wp_lo, b_p, out, TOKENS, EMBED, EMBED);
}

// round 6
// speedup vs baseline: 4.1015x; 1.4617x over previous
#include <cuda_runtime.h>
#include <cuda_fp16.h>
#include <math.h>
#include <stdint.h>

#define EMBED   1024
#define NHEAD   16
#define HD      64
#define BATCH   2
#define SEQ     2048
#define TOKENS  (BATCH * SEQ)      // 4096
#define QKV_N   (3 * EMBED)        // 3072

// ---------------------------------------------------------------------------
// Scratch
// ---------------------------------------------------------------------------
__device__ __half g_x_hi [(size_t)TOKENS * EMBED];
__device__ __half g_x_lo [(size_t)TOKENS * EMBED];
__device__ __half g_wqkv [(size_t)QKV_N * EMBED];
__device__ __half g_wp   [(size_t)EMBED * EMBED];
__device__ __half g_at_hi[(size_t)TOKENS * EMBED];
__device__ __half g_at_lo[(size_t)TOKENS * EMBED];
#define HEADELEMS ((size_t)BATCH * NHEAD * SEQ * HD)
__device__ __half g_q_hi[HEADELEMS], g_q_lo[HEADELEMS];
__device__ __half g_k[HEADELEMS], g_v[HEADELEMS];

// ---------------------------------------------------------------------------
// helpers
// ---------------------------------------------------------------------------
__device__ __forceinline__ uint32_t smem_u32(const void* p) {
    uint32_t a;
    asm("{ .reg .u64 t; cvta.to.shared.u64 t, %1; cvt.u32.u64 %0, t; }"
        : "=r"(a) : "l"(p));
    return a;
}
__device__ __forceinline__ void cp_async16(uint32_t s, const void* g) {
    asm volatile("cp.async.cg.shared.global [%0], [%1], 16;" :: "r"(s), "l"(g));
}
#define CP_COMMIT() asm volatile("cp.async.commit_group;" ::: "memory")
#define CP_WAIT1()  asm volatile("cp.async.wait_group 1;" ::: "memory")
#define CP_WAIT0()  asm volatile("cp.async.wait_group 0;" ::: "memory")

__device__ __forceinline__ void ldm_x4(uint32_t* r, uint32_t addr) {
    asm volatile("ldmatrix.sync.aligned.m8n8.x4.shared.b16 {%0,%1,%2,%3}, [%4];"
                 : "=r"(r[0]), "=r"(r[1]), "=r"(r[2]), "=r"(r[3]) : "r"(addr));
}
__device__ __forceinline__ void ldm_x4t(uint32_t* r, uint32_t addr) {
    asm volatile("ldmatrix.sync.aligned.m8n8.x4.trans.shared.b16 {%0,%1,%2,%3}, [%4];"
                 : "=r"(r[0]), "=r"(r[1]), "=r"(r[2]), "=r"(r[3]) : "r"(addr));
}
__device__ __forceinline__ void mma_f16(float* c, const uint32_t* a,
                                        uint32_t b0, uint32_t b1) {
    asm volatile("mma.sync.aligned.m16n8k16.row.col.f32.f16.f16.f32 "
                 "{%0,%1,%2,%3}, {%4,%5,%6,%7}, {%8,%9}, {%0,%1,%2,%3};"
                 : "+f"(c[0]), "+f"(c[1]), "+f"(c[2]), "+f"(c[3])
                 : "r"(a[0]), "r"(a[1]), "r"(a[2]), "r"(a[3]), "r"(b0), "r"(b1));
}
__device__ __forceinline__ void split2h(float x, float y, uint32_t& h, uint32_t& l) {
    __half hx = __float2half_rn(x), hy = __float2half_rn(y);
    __half lx = __float2half_rn(x - __half2float(hx));
    __half ly = __float2half_rn(y - __half2float(hy));
    __half2 hh = __halves2half2(hx, hy), ll = __halves2half2(lx, ly);
    h = *(uint32_t*)&hh; l = *(uint32_t*)&ll;
}
__device__ __forceinline__ uint32_t pack_h2(float x, float y) {
    __half2 v = __floats2half2_rn(x, y);
    return *(uint32_t*)&v;
}

// ---------------------------------------------------------------------------
// fp32 -> fp16 hi/lo split ; fp32 -> fp16 single
// ---------------------------------------------------------------------------
__global__ void split_kernel(const float4* __restrict__ in,
                             uint32_t* __restrict__ hi,
                             uint32_t* __restrict__ lo, int n4)
{
    int i = blockIdx.x * blockDim.x + threadIdx.x;
    if (i >= n4) return;
    float4 v = in[i];
    uint32_t h0, l0, h1, l1;
    split2h(v.x, v.y, h0, l0);
    split2h(v.z, v.w, h1, l1);
    hi[2 * i + 0] = h0; hi[2 * i + 1] = h1;
    lo[2 * i + 0] = l0; lo[2 * i + 1] = l1;
}
__global__ void tohalf_kernel(const float4* __restrict__ in,
                              uint32_t* __restrict__ out, int n4)
{
    int i = blockIdx.x * blockDim.x + threadIdx.x;
    if (i >= n4) return;
    float4 v = in[i];
    out[2 * i + 0] = pack_h2(v.x, v.y);
    out[2 * i + 1] = pack_h2(v.z, v.w);
}

// ---------------------------------------------------------------------------
// HMMA fp16 2-product GEMM: C = (Ah+Al) @ B^T + bias, A split / B single fp16.
// CTA 128x128, BK=32, 8 warps (64x32 warptile), 3-stage cp.async,
// single __syncthreads per chunk.
// MODE 0: fp32 C + bias. MODE 1: QKV epilogue -> per-head q(hi/lo fp16), k, v.
// ---------------------------------------------------------------------------
#define ROWB   80
#define TILE_B (128 * ROWB)    // 10240
#define STG_B  (3 * TILE_B)    // 30720 (Ah, Al, B)
#define G_SMEM (3 * STG_B)     // 92160

template <int MODE>
__global__ __launch_bounds__(256, 2)
void gemm_f16x2(const __half* __restrict__ Ah, const __half* __restrict__ Al,
                const __half* __restrict__ B,
                const float* __restrict__ bias, float* __restrict__ C,
                int M, int N, int K)
{
    extern __shared__ char smem[];
    const uint32_t sb = smem_u32(smem);
    const int tid  = threadIdx.x;
    const int wid  = tid >> 5;
    const int lane = tid & 31;
    const int warp_m = wid & 1;
    const int warp_n = wid >> 1;
    const int m0 = blockIdx.y * 128;
    const int n0 = blockIdx.x * 128;

    const int lr = tid >> 2;
    const int lc = (tid & 3) * 16;

    const __half* gA[3] = { Ah + (size_t)m0 * K, Al + (size_t)m0 * K,
                            B + (size_t)n0 * K };

    float acc[4][4][4];
#pragma unroll
    for (int i = 0; i < 4; i++)
#pragma unroll
        for (int j = 0; j < 4; j++)
#pragma unroll
            for (int f = 0; f < 4; f++) acc[i][j][f] = 0.0f;

    const int nk = K >> 5;

    // preload chunk 0 -> stage 0
#pragma unroll
    for (int t = 0; t < 3; t++) {
        uint32_t sT = sb + t * TILE_B;
        cp_async16(sT + lr * ROWB + lc,        (const char*)(gA[t] + (size_t)lr * K) + lc);
        cp_async16(sT + (lr + 64) * ROWB + lc, (const char*)(gA[t] + (size_t)(lr + 64) * K) + lc);
    }
    CP_COMMIT();

    const uint32_t a_off = (uint32_t)(warp_m * 64 + (lane & 15)) * ROWB + (lane >> 4) * 16;
    const uint32_t b_off = (uint32_t)(warp_n * 32 + (lane & 15)) * ROWB + (lane >> 4) * 16;

    int buf = 0, nxt = 1;
    for (int c = 0; c < nk; c++) {
        if (c + 1 < nk) {
            const int kb = (c + 1) * 64;   // byte offset along K
#pragma unroll
            for (int t = 0; t < 3; t++) {
                uint32_t sT = sb + nxt * STG_B + t * TILE_B;
                cp_async16(sT + lr * ROWB + lc,        (const char*)(gA[t] + (size_t)lr * K) + kb + lc);
                cp_async16(sT + (lr + 64) * ROWB + lc, (const char*)(gA[t] + (size_t)(lr + 64) * K) + kb + lc);
            }
            CP_COMMIT();
            CP_WAIT1();
        } else {
            CP_WAIT0();
        }
        __syncthreads();

        const uint32_t st = sb + buf * STG_B;
#pragma unroll
        for (int ks = 0; ks < 2; ks++) {
            const uint32_t ko = ks * 32;
            uint32_t ah[4][4], al[4][4], bf[2][4];
#pragma unroll
            for (int mt = 0; mt < 4; mt++) {
                ldm_x4(ah[mt], st + 0 * TILE_B + a_off + mt * 16 * ROWB + ko);
                ldm_x4(al[mt], st + 1 * TILE_B + a_off + mt * 16 * ROWB + ko);
            }
#pragma unroll
            for (int bt = 0; bt < 2; bt++)
                ldm_x4(bf[bt], st + 2 * TILE_B + b_off + bt * 16 * ROWB + ko);
#pragma unroll
            for (int mt = 0; mt < 4; mt++)
#pragma unroll
                for (int nt = 0; nt < 4; nt++) {
                    const int bt = nt >> 1, p = nt & 1;
                    mma_f16(acc[mt][nt], ah[mt], bf[bt][p], bf[bt][p + 2]);
                    mma_f16(acc[mt][nt], al[mt], bf[bt][p], bf[bt][p + 2]);
                }
        }
        buf = nxt; nxt = nxt + 1 == 3 ? 0 : nxt + 1;
    }

    const int gr = lane >> 2;
    const int gc = (lane & 3) << 1;
#pragma unroll
    for (int mt = 0; mt < 4; mt++) {
        const int row = m0 + warp_m * 64 + mt * 16 + gr;
#pragma unroll
        for (int nt = 0; nt < 4; nt++) {
            const int col = n0 + warp_n * 32 + nt * 8 + gc;
            const float b0 = bias[col], b1 = bias[col + 1];
            float x0 = acc[mt][nt][0] + b0, x1 = acc[mt][nt][1] + b1;
            float y0 = acc[mt][nt][2] + b0, y1 = acc[mt][nt][3] + b1;
            if (MODE == 0) {
                *(float2*)(C + (size_t)row * N + col)       = make_float2(x0, x1);
                *(float2*)(C + (size_t)(row + 8) * N + col) = make_float2(y0, y1);
            } else {
                const int t = col >> 10;             // 0=q 1=k 2=v
                const int h = (col >> 6) & (NHEAD - 1);
                const int d = col & (HD - 1);
                const int bb = row >> 11, sq = row & (SEQ - 1);
                const size_t dst = (((size_t)(bb * NHEAD + h) * SEQ) + sq) * HD + d;
                if (t == 0) {
                    x0 *= 0.125f; x1 *= 0.125f; y0 *= 0.125f; y1 *= 0.125f;
                    uint32_t hh, ll;
                    split2h(x0, x1, hh, ll);
                    *(uint32_t*)(g_q_hi + dst) = hh;
                    *(uint32_t*)(g_q_lo + dst) = ll;
                    split2h(y0, y1, hh, ll);
                    *(uint32_t*)(g_q_hi + dst + 8 * HD) = hh;
                    *(uint32_t*)(g_q_lo + dst + 8 * HD) = ll;
                } else {
                    __half* dp = (t == 1) ? g_k : g_v;
                    *(uint32_t*)(dp + dst)          = pack_h2(x0, x1);
                    *(uint32_t*)(dp + dst + 8 * HD) = pack_h2(y0, y1);
                }
            }
        }
    }
}

// ---------------------------------------------------------------------------
// HMMA flash attention (fp16 2-product: Q split, K/V single, P split).
// Q smem reused as KV buffers; 3 KV buffers, single sync per tile.
// ---------------------------------------------------------------------------
#define BQ    128
#define BKV   64
#define KROWB 144
#define F_T   (BKV * KROWB)        // 9216 (one KV tensor)
#define F_STG (2 * F_T)            // 18432 (K + V)
#define F_SMEM (3 * F_STG)         // 55296 (Q occupies bufs 0-1 initially)
#define NKV   (SEQ / BKV)          // 32

__global__ __launch_bounds__(256, 2)
void flash_f16(const __half* __restrict__ qh, const __half* __restrict__ ql,
               const __half* __restrict__ kk, const __half* __restrict__ vv,
               __half* __restrict__ oh, __half* __restrict__ ol)
{
    extern __shared__ char smem[];
    const uint32_t sb = smem_u32(smem);
    const int tid = threadIdx.x;
    const int wid = tid >> 5;
    const int lane = tid & 31;

    const int q0 = blockIdx.x * BQ;
    const int h  = blockIdx.y;
    const int b  = blockIdx.z;
    const size_t hoff = ((size_t)(b * NHEAD + h)) * SEQ * HD;

    // Q hi -> [0, 18432), Q lo -> [18432, 36864)
#pragma unroll
    for (int i = 0; i < 4; i++) {
        int chunk = tid + i * 256;           // 0..1023
        int row = chunk >> 3, col = (chunk & 7) * 16;
        cp_async16(sb + row * KROWB + col,
                   (const char*)(qh + hoff + (size_t)(q0 + row) * HD) + col);
        cp_async16(sb + F_STG + row * KROWB + col,
                   (const char*)(ql + hoff + (size_t)(q0 + row) * HD) + col);
    }
    CP_COMMIT();

    // KV tile 0 -> buffer 2 (offset 36864)
#pragma unroll
    for (int i = 0; i < 2; i++) {
        int chunk = tid + i * 256;
        int row = chunk >> 3, col = (chunk & 7) * 16;
        uint32_t s = sb + 2 * F_STG + row * KROWB + col;
        const size_t g = hoff + (size_t)row * HD;
        cp_async16(s + 0 * F_T, (const char*)(kk + g) + col);
        cp_async16(s + 1 * F_T, (const char*)(vv + g) + col);
    }
    CP_COMMIT();

    CP_WAIT1();          // Q done (KV0 may still fly)
    __syncthreads();

    uint32_t qfh[4][4], qfl[4][4];
    {
        const uint32_t qa = sb + (uint32_t)(wid * 16 + (lane & 15)) * KROWB + 16 * (lane >> 4);
#pragma unroll
        for (int kt = 0; kt < 4; kt++) {
            ldm_x4(qfh[kt], qa + kt * 32);
            ldm_x4(qfl[kt], qa + F_STG + kt * 32);
        }
    }
    __syncthreads();     // all warps done reading Q before buf0 refill

    float o[8][4];
#pragma unroll
    for (int nt = 0; nt < 8; nt++)
#pragma unroll
        for (int f = 0; f < 4; f++) o[nt][f] = 0.0f;
    float m0r = -INFINITY, m1r = -INFINITY, l0r = 0.0f, l1r = 0.0f;

    int buf = 2, nxt = 0;   // buf(t) = (t+2)%3
    for (int t = 0; t < NKV; t++) {
        if (t + 1 < NKV) {
            const int key0 = (t + 1) * BKV;
            const uint32_t dstb = sb + nxt * F_STG;
#pragma unroll
            for (int i = 0; i < 2; i++) {
                int chunk = tid + i * 256;
                int row = chunk >> 3, col = (chunk & 7) * 16;
                uint32_t s = dstb + row * KROWB + col;
                const size_t g = hoff + (size_t)(key0 + row) * HD;
                cp_async16(s + 0 * F_T, (const char*)(kk + g) + col);
                cp_async16(s + 1 * F_T, (const char*)(vv + g) + col);
            }
            CP_COMMIT();
            CP_WAIT1();
        } else {
            CP_WAIT0();
        }
        __syncthreads();

        const uint32_t kvb = sb + buf * F_STG;

        // S = Qh K^T + Ql K^T
        float s[8][4];
#pragma unroll
        for (int nt = 0; nt < 8; nt++)
#pragma unroll
            for (int f = 0; f < 4; f++) s[nt][f] = 0.0f;

#pragma unroll
        for (int ntp = 0; ntp < 4; ntp++) {
            const uint32_t ka = kvb + (uint32_t)(ntp * 16 + (lane & 15)) * KROWB + 16 * (lane >> 4);
#pragma unroll
            for (int kt = 0; kt < 4; kt++) {
                uint32_t kf[4];
                ldm_x4(kf, ka + kt * 32);
                mma_f16(s[2 * ntp],     qfh[kt], kf[0], kf[2]);
                mma_f16(s[2 * ntp],     qfl[kt], kf[0], kf[2]);
                mma_f16(s[2 * ntp + 1], qfh[kt], kf[1], kf[3]);
                mma_f16(s[2 * ntp + 1], qfl[kt], kf[1], kf[3]);
            }
        }

        // online softmax
        float mx0 = -INFINITY, mx1 = -INFINITY;
#pragma unroll
        for (int nt = 0; nt < 8; nt++) {
            mx0 = fmaxf(mx0, fmaxf(s[nt][0], s[nt][1]));
            mx1 = fmaxf(mx1, fmaxf(s[nt][2], s[nt][3]));
        }
        mx0 = fmaxf(mx0, __shfl_xor_sync(0xffffffffu, mx0, 1));
        mx0 = fmaxf(mx0, __shfl_xor_sync(0xffffffffu, mx0, 2));
        mx1 = fmaxf(mx1, __shfl_xor_sync(0xffffffffu, mx1, 1));
        mx1 = fmaxf(mx1, __shfl_xor_sync(0xffffffffu, mx1, 2));

        const float mn0 = fmaxf(m0r, mx0), mn1 = fmaxf(m1r, mx1);
        const float a0 = __expf(m0r - mn0), a1 = __expf(m1r - mn1);
        m0r = mn0; m1r = mn1;

        float rs0 = 0.0f, rs1 = 0.0f;
#pragma unroll
        for (int nt = 0; nt < 8; nt++) {
            s[nt][0] = __expf(s[nt][0] - mn0); s[nt][1] = __expf(s[nt][1] - mn0);
            s[nt][2] = __expf(s[nt][2] - mn1); s[nt][3] = __expf(s[nt][3] - mn1);
            rs0 += s[nt][0] + s[nt][1];
            rs1 += s[nt][2] + s[nt][3];
        }
        rs0 += __shfl_xor_sync(0xffffffffu, rs0, 1);
        rs0 += __shfl_xor_sync(0xffffffffu, rs0, 2);
        rs1 += __shfl_xor_sync(0xffffffffu, rs1, 1);
        rs1 += __shfl_xor_sync(0xffffffffu, rs1, 2);
        l0r = l0r * a0 + rs0;
        l1r = l1r * a1 + rs1;

#pragma unroll
        for (int nt = 0; nt < 8; nt++) {
            o[nt][0] *= a0; o[nt][1] *= a0;
            o[nt][2] *= a1; o[nt][3] *= a1;
        }

        // O += Ph V + Pl V
#pragma unroll
        for (int kt = 0; kt < 4; kt++) {
            uint32_t ph[4], pl[4];
            split2h(s[2 * kt][0],     s[2 * kt][1],     ph[0], pl[0]);
            split2h(s[2 * kt][2],     s[2 * kt][3],     ph[1], pl[1]);
            split2h(s[2 * kt + 1][0], s[2 * kt + 1][1], ph[2], pl[2]);
            split2h(s[2 * kt + 1][2], s[2 * kt + 1][3], ph[3], pl[3]);

            const uint32_t va = kvb + F_T + (uint32_t)(kt * 16 + (lane & 15)) * KROWB + 16 * (lane >> 4);
#pragma unroll
            for (int ntp = 0; ntp < 4; ntp++) {
                uint32_t vf[4];
                ldm_x4t(vf, va + ntp * 32);
                mma_f16(o[2 * ntp],     ph, vf[0], vf[1]);
                mma_f16(o[2 * ntp],     pl, vf[0], vf[1]);
                mma_f16(o[2 * ntp + 1], ph, vf[2], vf[3]);
                mma_f16(o[2 * ntp + 1], pl, vf[2], vf[3]);
            }
        }
        buf = nxt; nxt = nxt + 1 == 3 ? 0 : nxt + 1;
    }

    const float inv0 = 1.0f / l0r, inv1 = 1.0f / l1r;
    const int gr = lane >> 2, gc = (lane & 3) * 2;
    const size_t row0 = (size_t)(b * SEQ + q0 + wid * 16 + gr) * EMBED + h * HD;
    const size_t row1 = row0 + 8 * EMBED;
#pragma unroll
    for (int nt = 0; nt < 8; nt++) {
        const int d = nt * 8 + gc;
        uint32_t hh, ll;
        split2h(o[nt][0] * inv0, o[nt][1] * inv0, hh, ll);
        *(uint32_t*)(oh + row0 + d) = hh;
        *(uint32_t*)(ol + row0 + d) = ll;
        split2h(o[nt][2] * inv1, o[nt][3] * inv1, hh, ll);
        *(uint32_t*)(oh + row1 + d) = hh;
        *(uint32_t*)(ol + row1 + d) = ll;
    }
}

// ---------------------------------------------------------------------------
extern "C" void kernel_launch(void* const* d_in, const int* in_sizes, int n_in,
                              void* d_out, int out_size)
{
    const float* x     = (const float*)d_in[0];
    const float* W_qkv = (const float*)d_in[1];
    const float* b_qkv = (const float*)d_in[2];
    const float* W_p   = (const float*)d_in[3];
    const float* b_p   = (const float*)d_in[4];
    float* out = (float*)d_out;

    __half *x_hi, *x_lo, *wq, *wp, *at_hi, *at_lo;
    __half *q_hi, *q_lo, *kv_k, *kv_v;
    cudaGetSymbolAddress((void**)&x_hi,  g_x_hi);
    cudaGetSymbolAddress((void**)&x_lo,  g_x_lo);
    cudaGetSymbolAddress((void**)&wq,    g_wqkv);
    cudaGetSymbolAddress((void**)&wp,    g_wp);
    cudaGetSymbolAddress((void**)&at_hi, g_at_hi);
    cudaGetSymbolAddress((void**)&at_lo, g_at_lo);
    cudaGetSymbolAddress((void**)&q_hi,  g_q_hi);
    cudaGetSymbolAddress((void**)&q_lo,  g_q_lo);
    cudaGetSymbolAddress((void**)&kv_k,  g_k);
    cudaGetSymbolAddress((void**)&kv_v,  g_v);

    cudaFuncSetAttribute(gemm_f16x2<0>, cudaFuncAttributeMaxDynamicSharedMemorySize, G_SMEM);
    cudaFuncSetAttribute(gemm_f16x2<1>, cudaFuncAttributeMaxDynamicSharedMemorySize, G_SMEM);
    cudaFuncSetAttribute(flash_f16,     cudaFuncAttributeMaxDynamicSharedMemorySize, F_SMEM);

    // input conversions
    {
        int n4 = TOKENS * EMBED / 4;
        split_kernel<<<(n4 + 255) / 256, 256>>>((const float4*)x,
            (uint32_t*)x_hi, (uint32_t*)x_lo, n4);
    }
    {
        int n4 = QKV_N * EMBED / 4;
        tohalf_kernel<<<(n4 + 255) / 256, 256>>>((const float4*)W_qkv, (uint32_t*)wq, n4);
    }
    {
        int n4 = EMBED * EMBED / 4;
        tohalf_kernel<<<(n4 + 255) / 256, 256>>>((const float4*)W_p, (uint32_t*)wp, n4);
    }

    // QKV projection, epilogue writes per-head q(hi/lo)/k/v
    gemm_f16x2<1><<<dim3(QKV_N / 128, TOKENS / 128), 256, G_SMEM>>>(
        x_hi, x_lo, wq, b_qkv, nullptr, TOKENS, QKV_N, EMBED);

    // attention
    flash_f16<<<dim3(SEQ / BQ, NHEAD, BATCH), 256, F_SMEM>>>(
        q_hi, q_lo, kv_k, kv_v, at_hi, at_lo);

    // output projection
    gemm_f16x2<0><<<dim3(EMBED / 128, TOKENS / 128), 256, G_SMEM>>>(
        at_hi, at_lo, wp, b_p, out, TOKENS, EMBED, EMBED);
}

// round 7
// speedup vs baseline: 7.1332x; 1.7392x over previous
#include <cuda_runtime.h>
#include <cuda_fp16.h>
#include <math.h>
#include <stdint.h>

#define EMBED   1024
#define NHEAD   16
#define HD      64
#define BATCH   2
#define SEQ     2048
#define TOKENS  (BATCH * SEQ)      // 4096
#define QKV_N   (3 * EMBED)        // 3072

// ---------------------------------------------------------------------------
// Scratch
// ---------------------------------------------------------------------------
__device__ __half g_x  [(size_t)TOKENS * EMBED];
__device__ __half g_wqkv[(size_t)QKV_N * EMBED];
__device__ __half g_wp [(size_t)EMBED * EMBED];
__device__ __half g_at [(size_t)TOKENS * EMBED];
#define HEADELEMS ((size_t)BATCH * NHEAD * SEQ * HD)
__device__ __half g_q[HEADELEMS], g_k[HEADELEMS], g_v[HEADELEMS];

// ---------------------------------------------------------------------------
// helpers
// ---------------------------------------------------------------------------
__device__ __forceinline__ uint32_t smem_u32(const void* p) {
    uint32_t a;
    asm("{ .reg .u64 t; cvta.to.shared.u64 t, %1; cvt.u32.u64 %0, t; }"
        : "=r"(a) : "l"(p));
    return a;
}
__device__ __forceinline__ void cp_async16(uint32_t s, const void* g) {
    asm volatile("cp.async.cg.shared.global [%0], [%1], 16;" :: "r"(s), "l"(g));
}
#define CP_COMMIT() asm volatile("cp.async.commit_group;" ::: "memory")
#define CP_WAIT1()  asm volatile("cp.async.wait_group 1;" ::: "memory")
#define CP_WAIT0()  asm volatile("cp.async.wait_group 0;" ::: "memory")

__device__ __forceinline__ void ldm_x4(uint32_t* r, uint32_t addr) {
    asm volatile("ldmatrix.sync.aligned.m8n8.x4.shared.b16 {%0,%1,%2,%3}, [%4];"
                 : "=r"(r[0]), "=r"(r[1]), "=r"(r[2]), "=r"(r[3]) : "r"(addr));
}
__device__ __forceinline__ void ldm_x4t(uint32_t* r, uint32_t addr) {
    asm volatile("ldmatrix.sync.aligned.m8n8.x4.trans.shared.b16 {%0,%1,%2,%3}, [%4];"
                 : "=r"(r[0]), "=r"(r[1]), "=r"(r[2]), "=r"(r[3]) : "r"(addr));
}
__device__ __forceinline__ void mma_f16(float* c, const uint32_t* a,
                                        uint32_t b0, uint32_t b1) {
    asm volatile("mma.sync.aligned.m16n8k16.row.col.f32.f16.f16.f32 "
                 "{%0,%1,%2,%3}, {%4,%5,%6,%7}, {%8,%9}, {%0,%1,%2,%3};"
                 : "+f"(c[0]), "+f"(c[1]), "+f"(c[2]), "+f"(c[3])
                 : "r"(a[0]), "r"(a[1]), "r"(a[2]), "r"(a[3]), "r"(b0), "r"(b1));
}
__device__ __forceinline__ uint32_t pack_h2(float x, float y) {
    __half2 v = __floats2half2_rn(x, y);
    return *(uint32_t*)&v;
}

// ---------------------------------------------------------------------------
// fp32 -> fp16
// ---------------------------------------------------------------------------
__global__ void tohalf_kernel(const float4* __restrict__ in,
                              uint32_t* __restrict__ out, int n4)
{
    int i = blockIdx.x * blockDim.x + threadIdx.x;
    if (i >= n4) return;
    float4 v = in[i];
    out[2 * i + 0] = pack_h2(v.x, v.y);
    out[2 * i + 1] = pack_h2(v.z, v.w);
}

// ---------------------------------------------------------------------------
// HMMA fp16 GEMM: C[m][n] = sum_k A[m][k]*B[n][k] + bias[n]
// CTA 128x128, BK=32, 8 warps (64x32 warptile), 3-stage cp.async, 1 sync/chunk.
// MODE 0: fp32 C + bias. MODE 1: QKV epilogue -> per-head fp16 q(*1/8)/k/v.
// ---------------------------------------------------------------------------
#define ROWB   80
#define TILE_B (128 * ROWB)    // 10240
#define STG_B  (2 * TILE_B)    // 20480 (A, B)
#define G_SMEM (3 * STG_B)     // 61440

template <int MODE>
__global__ __launch_bounds__(256, 2)
void gemm_f16(const __half* __restrict__ A, const __half* __restrict__ B,
              const float* __restrict__ bias, float* __restrict__ C,
              int M, int N, int K)
{
    extern __shared__ char smem[];
    const uint32_t sb = smem_u32(smem);
    const int tid  = threadIdx.x;
    const int wid  = tid >> 5;
    const int lane = tid & 31;
    const int warp_m = wid & 1;
    const int warp_n = wid >> 1;
    const int m0 = blockIdx.y * 128;
    const int n0 = blockIdx.x * 128;

    const int lr = tid >> 2;
    const int lc = (tid & 3) * 16;

    const __half* gA[2] = { A + (size_t)m0 * K, B + (size_t)n0 * K };

    float acc[4][4][4];
#pragma unroll
    for (int i = 0; i < 4; i++)
#pragma unroll
        for (int j = 0; j < 4; j++)
#pragma unroll
            for (int f = 0; f < 4; f++) acc[i][j][f] = 0.0f;

    const int nk = K >> 5;

#pragma unroll
    for (int t = 0; t < 2; t++) {
        uint32_t sT = sb + t * TILE_B;
        cp_async16(sT + lr * ROWB + lc,        (const char*)(gA[t] + (size_t)lr * K) + lc);
        cp_async16(sT + (lr + 64) * ROWB + lc, (const char*)(gA[t] + (size_t)(lr + 64) * K) + lc);
    }
    CP_COMMIT();

    const uint32_t a_off = (uint32_t)(warp_m * 64 + (lane & 15)) * ROWB + (lane >> 4) * 16;
    const uint32_t b_off = (uint32_t)(warp_n * 32 + (lane & 15)) * ROWB + (lane >> 4) * 16;

    int buf = 0, nxt = 1;
    for (int c = 0; c < nk; c++) {
        if (c + 1 < nk) {
            const int kb = (c + 1) * 64;
#pragma unroll
            for (int t = 0; t < 2; t++) {
                uint32_t sT = sb + nxt * STG_B + t * TILE_B;
                cp_async16(sT + lr * ROWB + lc,        (const char*)(gA[t] + (size_t)lr * K) + kb + lc);
                cp_async16(sT + (lr + 64) * ROWB + lc, (const char*)(gA[t] + (size_t)(lr + 64) * K) + kb + lc);
            }
            CP_COMMIT();
            CP_WAIT1();
        } else {
            CP_WAIT0();
        }
        __syncthreads();

        const uint32_t st = sb + buf * STG_B;
#pragma unroll
        for (int ks = 0; ks < 2; ks++) {
            const uint32_t ko = ks * 32;
            uint32_t af[4][4], bf[2][4];
#pragma unroll
            for (int mt = 0; mt < 4; mt++)
                ldm_x4(af[mt], st + a_off + mt * 16 * ROWB + ko);
#pragma unroll
            for (int bt = 0; bt < 2; bt++)
                ldm_x4(bf[bt], st + TILE_B + b_off + bt * 16 * ROWB + ko);
#pragma unroll
            for (int mt = 0; mt < 4; mt++)
#pragma unroll
                for (int nt = 0; nt < 4; nt++) {
                    const int bt = nt >> 1, p = nt & 1;
                    mma_f16(acc[mt][nt], af[mt], bf[bt][p], bf[bt][p + 2]);
                }
        }
        buf = nxt; nxt = nxt + 1 == 3 ? 0 : nxt + 1;
    }

    const int gr = lane >> 2;
    const int gc = (lane & 3) << 1;
#pragma unroll
    for (int mt = 0; mt < 4; mt++) {
        const int row = m0 + warp_m * 64 + mt * 16 + gr;
#pragma unroll
        for (int nt = 0; nt < 4; nt++) {
            const int col = n0 + warp_n * 32 + nt * 8 + gc;
            const float b0 = bias[col], b1 = bias[col + 1];
            float x0 = acc[mt][nt][0] + b0, x1 = acc[mt][nt][1] + b1;
            float y0 = acc[mt][nt][2] + b0, y1 = acc[mt][nt][3] + b1;
            if (MODE == 0) {
                *(float2*)(C + (size_t)row * N + col)       = make_float2(x0, x1);
                *(float2*)(C + (size_t)(row + 8) * N + col) = make_float2(y0, y1);
            } else {
                const int t = col >> 10;             // 0=q 1=k 2=v
                const int h = (col >> 6) & (NHEAD - 1);
                const int d = col & (HD - 1);
                const int bb = row >> 11, sq = row & (SEQ - 1);
                const size_t dst = (((size_t)(bb * NHEAD + h) * SEQ) + sq) * HD + d;
                __half* dp;
                if (t == 0) {
                    dp = g_q;
                    x0 *= 0.125f; x1 *= 0.125f; y0 *= 0.125f; y1 *= 0.125f;
                } else dp = (t == 1) ? g_k : g_v;
                *(uint32_t*)(dp + dst)          = pack_h2(x0, x1);
                *(uint32_t*)(dp + dst + 8 * HD) = pack_h2(y0, y1);
            }
        }
    }
}

// ---------------------------------------------------------------------------
// HMMA flash attention (pure fp16 operands, fp32 accum + softmax).
// CTA = 128 queries of one (b,h); 8 warps. 3 KV buffers (Q region reused),
// single __syncthreads per tile.
// ---------------------------------------------------------------------------
#define BQ    128
#define BKV   64
#define KROWB 144
#define F_T   (BKV * KROWB)        // 9216 (one KV tensor)
#define F_STG (2 * F_T)            // 18432 (K + V) == Q region size
#define F_SMEM (3 * F_STG)         // 55296
#define NKV   (SEQ / BKV)          // 32

__global__ __launch_bounds__(256, 2)
void flash_f16(const __half* __restrict__ qq, const __half* __restrict__ kk,
               const __half* __restrict__ vv, __half* __restrict__ oo)
{
    extern __shared__ char smem[];
    const uint32_t sb = smem_u32(smem);
    const int tid = threadIdx.x;
    const int wid = tid >> 5;
    const int lane = tid & 31;

    const int q0 = blockIdx.x * BQ;
    const int h  = blockIdx.y;
    const int b  = blockIdx.z;
    const size_t hoff = ((size_t)(b * NHEAD + h)) * SEQ * HD;

    // Q (128 x 64 fp16) -> buffer 0
#pragma unroll
    for (int i = 0; i < 4; i++) {
        int chunk = tid + i * 256;           // 0..1023
        int row = chunk >> 3, col = (chunk & 7) * 16;
        cp_async16(sb + row * KROWB + col,
                   (const char*)(qq + hoff + (size_t)(q0 + row) * HD) + col);
    }
    CP_COMMIT();

    // KV tile 0 -> buffer 1
#pragma unroll
    for (int i = 0; i < 2; i++) {
        int chunk = tid + i * 256;
        int row = chunk >> 3, col = (chunk & 7) * 16;
        uint32_t s = sb + F_STG + row * KROWB + col;
        const size_t g = hoff + (size_t)row * HD;
        cp_async16(s + 0 * F_T, (const char*)(kk + g) + col);
        cp_async16(s + 1 * F_T, (const char*)(vv + g) + col);
    }
    CP_COMMIT();

    CP_WAIT1();          // Q done
    __syncthreads();

    uint32_t qf[4][4];
    {
        const uint32_t qa = sb + (uint32_t)(wid * 16 + (lane & 15)) * KROWB + 16 * (lane >> 4);
#pragma unroll
        for (int kt = 0; kt < 4; kt++)
            ldm_x4(qf[kt], qa + kt * 32);
    }
    __syncthreads();     // Q reads complete before buffer 0 is refilled (t=1)

    float o[8][4];
#pragma unroll
    for (int nt = 0; nt < 8; nt++)
#pragma unroll
        for (int f = 0; f < 4; f++) o[nt][f] = 0.0f;
    float m0r = -INFINITY, m1r = -INFINITY, l0r = 0.0f, l1r = 0.0f;

    int buf = 1, nxt = 2;   // read buf(t)=(t+1)%3, fill nxt=(t+2)%3
    for (int t = 0; t < NKV; t++) {
        if (t + 1 < NKV) {
            const int key0 = (t + 1) * BKV;
            const uint32_t dstb = sb + nxt * F_STG;
#pragma unroll
            for (int i = 0; i < 2; i++) {
                int chunk = tid + i * 256;
                int row = chunk >> 3, col = (chunk & 7) * 16;
                uint32_t s = dstb + row * KROWB + col;
                const size_t g = hoff + (size_t)(key0 + row) * HD;
                cp_async16(s + 0 * F_T, (const char*)(kk + g) + col);
                cp_async16(s + 1 * F_T, (const char*)(vv + g) + col);
            }
            CP_COMMIT();
            CP_WAIT1();
        } else {
            CP_WAIT0();
        }
        __syncthreads();

        const uint32_t kvb = sb + buf * F_STG;

        // S = Q K^T
        float s[8][4];
#pragma unroll
        for (int nt = 0; nt < 8; nt++)
#pragma unroll
            for (int f = 0; f < 4; f++) s[nt][f] = 0.0f;

#pragma unroll
        for (int ntp = 0; ntp < 4; ntp++) {
            const uint32_t ka = kvb + (uint32_t)(ntp * 16 + (lane & 15)) * KROWB + 16 * (lane >> 4);
#pragma unroll
            for (int kt = 0; kt < 4; kt++) {
                uint32_t kf[4];
                ldm_x4(kf, ka + kt * 32);
                mma_f16(s[2 * ntp],     qf[kt], kf[0], kf[2]);
                mma_f16(s[2 * ntp + 1], qf[kt], kf[1], kf[3]);
            }
        }

        // online softmax
        float mx0 = -INFINITY, mx1 = -INFINITY;
#pragma unroll
        for (int nt = 0; nt < 8; nt++) {
            mx0 = fmaxf(mx0, fmaxf(s[nt][0], s[nt][1]));
            mx1 = fmaxf(mx1, fmaxf(s[nt][2], s[nt][3]));
        }
        mx0 = fmaxf(mx0, __shfl_xor_sync(0xffffffffu, mx0, 1));
        mx0 = fmaxf(mx0, __shfl_xor_sync(0xffffffffu, mx0, 2));
        mx1 = fmaxf(mx1, __shfl_xor_sync(0xffffffffu, mx1, 1));
        mx1 = fmaxf(mx1, __shfl_xor_sync(0xffffffffu, mx1, 2));

        const float mn0 = fmaxf(m0r, mx0), mn1 = fmaxf(m1r, mx1);
        const float a0 = __expf(m0r - mn0), a1 = __expf(m1r - mn1);
        m0r = mn0; m1r = mn1;

        float rs0 = 0.0f, rs1 = 0.0f;
#pragma unroll
        for (int nt = 0; nt < 8; nt++) {
            s[nt][0] = __expf(s[nt][0] - mn0); s[nt][1] = __expf(s[nt][1] - mn0);
            s[nt][2] = __expf(s[nt][2] - mn1); s[nt][3] = __expf(s[nt][3] - mn1);
            rs0 += s[nt][0] + s[nt][1];
            rs1 += s[nt][2] + s[nt][3];
        }
        rs0 += __shfl_xor_sync(0xffffffffu, rs0, 1);
        rs0 += __shfl_xor_sync(0xffffffffu, rs0, 2);
        rs1 += __shfl_xor_sync(0xffffffffu, rs1, 1);
        rs1 += __shfl_xor_sync(0xffffffffu, rs1, 2);
        l0r = l0r * a0 + rs0;
        l1r = l1r * a1 + rs1;

#pragma unroll
        for (int nt = 0; nt < 8; nt++) {
            o[nt][0] *= a0; o[nt][1] *= a0;
            o[nt][2] *= a1; o[nt][3] *= a1;
        }

        // O += P V
#pragma unroll
        for (int kt = 0; kt < 4; kt++) {
            uint32_t pf[4];
            pf[0] = pack_h2(s[2 * kt][0],     s[2 * kt][1]);
            pf[1] = pack_h2(s[2 * kt][2],     s[2 * kt][3]);
            pf[2] = pack_h2(s[2 * kt + 1][0], s[2 * kt + 1][1]);
            pf[3] = pack_h2(s[2 * kt + 1][2], s[2 * kt + 1][3]);

            const uint32_t va = kvb + F_T + (uint32_t)(kt * 16 + (lane & 15)) * KROWB + 16 * (lane >> 4);
#pragma unroll
            for (int ntp = 0; ntp < 4; ntp++) {
                uint32_t vf[4];
                ldm_x4t(vf, va + ntp * 32);
                mma_f16(o[2 * ntp],     pf, vf[0], vf[1]);
                mma_f16(o[2 * ntp + 1], pf, vf[2], vf[3]);
            }
        }
        buf = nxt; nxt = nxt + 1 == 3 ? 0 : nxt + 1;
    }

    const float inv0 = 1.0f / l0r, inv1 = 1.0f / l1r;
    const int gr = lane >> 2, gc = (lane & 3) * 2;
    const size_t row0 = (size_t)(b * SEQ + q0 + wid * 16 + gr) * EMBED + h * HD;
    const size_t row1 = row0 + 8 * EMBED;
#pragma unroll
    for (int nt = 0; nt < 8; nt++) {
        const int d = nt * 8 + gc;
        *(uint32_t*)(oo + row0 + d) = pack_h2(o[nt][0] * inv0, o[nt][1] * inv0);
        *(uint32_t*)(oo + row1 + d) = pack_h2(o[nt][2] * inv1, o[nt][3] * inv1);
    }
}

// ---------------------------------------------------------------------------
extern "C" void kernel_launch(void* const* d_in, const int* in_sizes, int n_in,
                              void* d_out, int out_size)
{
    const float* x     = (const float*)d_in[0];
    const float* W_qkv = (const float*)d_in[1];
    const float* b_qkv = (const float*)d_in[2];
    const float* W_p   = (const float*)d_in[3];
    const float* b_p   = (const float*)d_in[4];
    float* out = (float*)d_out;

    __half *xh, *wq, *wp, *at, *q, *k, *v;
    cudaGetSymbolAddress((void**)&xh, g_x);
    cudaGetSymbolAddress((void**)&wq, g_wqkv);
    cudaGetSymbolAddress((void**)&wp, g_wp);
    cudaGetSymbolAddress((void**)&at, g_at);
    cudaGetSymbolAddress((void**)&q,  g_q);
    cudaGetSymbolAddress((void**)&k,  g_k);
    cudaGetSymbolAddress((void**)&v,  g_v);

    cudaFuncSetAttribute(gemm_f16<0>, cudaFuncAttributeMaxDynamicSharedMemorySize, G_SMEM);
    cudaFuncSetAttribute(gemm_f16<1>, cudaFuncAttributeMaxDynamicSharedMemorySize, G_SMEM);
    cudaFuncSetAttribute(flash_f16,   cudaFuncAttributeMaxDynamicSharedMemorySize, F_SMEM);

    // conversions
    {
        int n4 = TOKENS * EMBED / 4;
        tohalf_kernel<<<(n4 + 255) / 256, 256>>>((const float4*)x, (uint32_t*)xh, n4);
    }
    {
        int n4 = QKV_N * EMBED / 4;
        tohalf_kernel<<<(n4 + 255) / 256, 256>>>((const float4*)W_qkv, (uint32_t*)wq, n4);
    }
    {
        int n4 = EMBED * EMBED / 4;
        tohalf_kernel<<<(n4 + 255) / 256, 256>>>((const float4*)W_p, (uint32_t*)wp, n4);
    }

    // QKV projection -> per-head q/k/v
    gemm_f16<1><<<dim3(QKV_N / 128, TOKENS / 128), 256, G_SMEM>>>(
        xh, wq, b_qkv, nullptr, TOKENS, QKV_N, EMBED);

    // attention
    flash_f16<<<dim3(SEQ / BQ, NHEAD, BATCH), 256, F_SMEM>>>(q, k, v, at);

    // output projection
    gemm_f16<0><<<dim3(EMBED / 128, TOKENS / 128), 256, G_SMEM>>>(
        at, wp, b_p, out, TOKENS, EMBED, EMBED);
}